// round 15
// baseline (speedup 1.0000x reference)
#include <cuda_runtime.h>
#include <cuda_bf16.h>
#include <stdint.h>

#define T_  128
#define B_  64
#define D_  1024
#define TB_ (T_*B_)
#define D3_ (3*D_)
#define D9_ (9*D_)

typedef unsigned long long ull;

// ---------------- static scratch (no allocation anywhere) ----------------
__device__ float g_FAg[TB_*D_];
__device__ float g_Sinv[TB_*D_];
__device__ float g_S[TB_*D_];
__device__ float g_GI[TB_*D3_];
__device__ float g_Wbq[B_*D_];
__device__ float g_Wbm[B_*D_];
__device__ float g_rc[B_*D_];
__device__ float g_rcq[B_*D_];
__device__ float g_h0[B_*D_];
__device__ float g_h1[B_*D_];
__device__ float g_m[B_*D_];
__device__ float g_m2[B_*D_];
__device__ float g_gi[B_*D3_];
__device__ float g_gh[B_*D3_];
__device__ int   g_barrier;

// bf16 split buffers
__device__ __nv_bfloat16 g_bAh[TB_*D_];
__device__ __nv_bfloat16 g_bAl[TB_*D_];
__device__ __nv_bfloat16 g_FAh[TB_*D_];
__device__ __nv_bfloat16 g_FAl[TB_*D_];
__device__ __nv_bfloat16 g_FBh[TB_*D_];
__device__ __nv_bfloat16 g_FBl[TB_*D_];
__device__ __nv_bfloat16 g_FCh[TB_*D_];
__device__ __nv_bfloat16 g_FCl[TB_*D_];
__device__ __nv_bfloat16 g_W1h[D_*D9_];
__device__ __nv_bfloat16 g_W1l[D_*D9_];
__device__ __nv_bfloat16 g_W2h[D_*D_];
__device__ __nv_bfloat16 g_W2l[D_*D_];
__device__ __nv_bfloat16 g_Wihh[D3_*D_];
__device__ __nv_bfloat16 g_Wihl[D3_*D_];

// ---------------- helpers ----------------
__device__ __forceinline__ void ffma2(ull& c, ull a, ull b) {
    asm("fma.rn.f32x2 %0, %1, %2, %0;" : "+l"(c) : "l"(a), "l"(b));
}
__device__ __forceinline__ ull pk(float lo, float hi) {
    ull r; asm("mov.b64 %0, {%1, %2};" : "=l"(r) : "f"(lo), "f"(hi)); return r;
}
__device__ __forceinline__ float2 upk(ull a) {
    float2 v; asm("mov.b64 {%0, %1}, %2;" : "=f"(v.x), "=f"(v.y) : "l"(a)); return v;
}
__device__ __forceinline__ float sum2(ull a) { float2 v = upk(a); return v.x + v.y; }
__device__ __forceinline__ float sigf(float x)     { return 1.f / (1.f + __expf(-x)); }
__device__ __forceinline__ float tanhfast(float x) { return 2.f / (1.f + __expf(-2.f*x)) - 1.f; }

__device__ __forceinline__ void cpasync16(uint32_t dst, const void* src) {
    asm volatile("cp.async.cg.shared.global [%0], [%1], 16;" :: "r"(dst), "l"(src));
}
__device__ __forceinline__ void cpcommit() { asm volatile("cp.async.commit_group;"); }
__device__ __forceinline__ void cpwait2()  { asm volatile("cp.async.wait_group 2;"); }
__device__ __forceinline__ void cpwait1()  { asm volatile("cp.async.wait_group 1;"); }
__device__ __forceinline__ void cpwait0()  { asm volatile("cp.async.wait_group 0;"); }

__device__ __forceinline__ void ldmx4(uint32_t addr, uint32_t* r) {
    asm volatile("ldmatrix.sync.aligned.m8n8.x4.shared.b16 {%0,%1,%2,%3}, [%4];"
                 : "=r"(r[0]), "=r"(r[1]), "=r"(r[2]), "=r"(r[3]) : "r"(addr));
}

#define MMA_BF16(c, a, b0, b1) \
    asm volatile("mma.sync.aligned.m16n8k16.row.col.f32.bf16.bf16.f32 " \
                 "{%0,%1,%2,%3}, {%4,%5,%6,%7}, {%8,%9}, {%0,%1,%2,%3};" \
                 : "+f"((c)[0]), "+f"((c)[1]), "+f"((c)[2]), "+f"((c)[3]) \
                 : "r"((a)[0]), "r"((a)[1]), "r"((a)[2]), "r"((a)[3]), \
                   "r"(b0), "r"(b1))

__device__ __forceinline__ void bsplit4(__nv_bfloat16* hi, __nv_bfloat16* lo, int i,
                                        float x, float y, float z, float w)
{
    __nv_bfloat16 hx = __float2bfloat16(x), hy = __float2bfloat16(y);
    __nv_bfloat16 hz = __float2bfloat16(z), hw = __float2bfloat16(w);
    ((__nv_bfloat162*)hi)[2*i]   = __nv_bfloat162(hx, hy);
    ((__nv_bfloat162*)hi)[2*i+1] = __nv_bfloat162(hz, hw);
    ((__nv_bfloat162*)lo)[2*i]   = __nv_bfloat162(__float2bfloat16(x - __bfloat162float(hx)),
                                                  __float2bfloat16(y - __bfloat162float(hy)));
    ((__nv_bfloat162*)lo)[2*i+1] = __nv_bfloat162(__float2bfloat16(z - __bfloat162float(hz)),
                                                  __float2bfloat16(w - __bfloat162float(hw)));
}

// ================= mma.sync split-bf16 GEMM with K-segment fusion =================
// C[M=8192, N] (+)= sum_seg (Ah_s + Al_s) @ (B rows at kofs_s)^T   (Al*Bl dropped)
struct TGSegs {
    const __nv_bfloat16* Ah[4];
    const __nv_bfloat16* Al[4];
    int kofs[4];
    int nseg;
};

#define KC      32
#define PITCHB  80u
#define TILE_B  (128u * PITCHB)
#define BUF_B   (4u * TILE_B)
#define TGS_SMEM (2 * BUF_B)

__global__ __launch_bounds__(256) void tgemm_kernel(
    TGSegs segs,
    const __nv_bfloat16* __restrict__ Bh, const __nv_bfloat16* __restrict__ Bl,
    int ldB, float* __restrict__ C, int ldC, int accum)
{
    extern __shared__ __align__(16) char smraw[];
    const uint32_t sb = (uint32_t)__cvta_generic_to_shared(smraw);

    const int tid  = threadIdx.x;
    const int wid  = tid >> 5;
    const int lane = tid & 31;
    const int bm   = blockIdx.y * 128;
    const int bn   = blockIdx.x * 128;
    const int wm   = wid & 3;
    const int wn   = wid >> 2;

    float acc[2][8][4];
#pragma unroll
    for (int i = 0; i < 2; i++)
#pragma unroll
        for (int j = 0; j < 8; j++)
#pragma unroll
            for (int k = 0; k < 4; k++) acc[i][j][k] = 0.f;

    auto stage = [&](int buf, int k0g) {
        int seg = k0g >> 10;
        int kl  = k0g & 1023;
        const __nv_bfloat16* sAh = segs.Ah[seg];
        const __nv_bfloat16* sAl = segs.Al[seg];
        int bo = segs.kofs[seg] + kl;
        uint32_t base = sb + (uint32_t)buf * BUF_B;
#pragma unroll
        for (int r = 0; r < 8; r++) {
            int id   = tid + 256 * r;
            int tile = id >> 9;
            int row  = (id >> 2) & 127;
            int g    = id & 3;
            uint32_t daddr = base + (uint32_t)tile * TILE_B + (uint32_t)row * PITCHB + (uint32_t)g * 16u;
            const __nv_bfloat16* src;
            if      (tile == 0) src = sAh + (size_t)(bm + row) * 1024 + kl + g * 8;
            else if (tile == 1) src = sAl + (size_t)(bm + row) * 1024 + kl + g * 8;
            else if (tile == 2) src = Bh + (size_t)(bn + row) * ldB + bo + g * 8;
            else                src = Bl + (size_t)(bn + row) * ldB + bo + g * 8;
            cpasync16(daddr, src);
        }
    };

    const int NCH = segs.nseg * (1024 / KC);
    stage(0, 0); cpcommit();

    for (int ch = 0; ch < NCH; ch++) {
        if (ch + 1 < NCH) { stage((ch + 1) & 1, (ch + 1) * KC); cpcommit(); cpwait1(); }
        else              { cpwait0(); }
        __syncthreads();

        uint32_t base = sb + (uint32_t)(ch & 1) * BUF_B;
#pragma unroll
        for (int ks = 0; ks < 2; ks++) {
            uint32_t ah[2][4], al[2][4], bh[4][4], bl[4][4];
#pragma unroll
            for (int tm = 0; tm < 2; tm++) {
                uint32_t row = (uint32_t)(wm * 32 + tm * 16 + (lane & 15));
                uint32_t addr = base + row * PITCHB + (uint32_t)(ks * 32) + (uint32_t)((lane >> 4) * 16);
                ldmx4(addr, ah[tm]);
                ldmx4(addr + TILE_B, al[tm]);
            }
#pragma unroll
            for (int tb = 0; tb < 4; tb++) {
                uint32_t rn = (uint32_t)(wn * 64 + tb * 16 + ((lane >> 4) << 3) + (lane & 7));
                uint32_t addr = base + 2u * TILE_B + rn * PITCHB + (uint32_t)(ks * 32) + (uint32_t)(((lane >> 3) & 1) * 16);
                ldmx4(addr, bh[tb]);
                ldmx4(addr + TILE_B, bl[tb]);
            }
#pragma unroll
            for (int tm = 0; tm < 2; tm++)
#pragma unroll
                for (int tn = 0; tn < 8; tn++) {
                    int tb = tn >> 1, s = (tn & 1) * 2;
                    MMA_BF16(acc[tm][tn], ah[tm], bh[tb][s], bh[tb][s + 1]);
                    MMA_BF16(acc[tm][tn], ah[tm], bl[tb][s], bl[tb][s + 1]);
                    MMA_BF16(acc[tm][tn], al[tm], bh[tb][s], bh[tb][s + 1]);
                }
        }
        __syncthreads();
    }

    const int r0 = bm + wm * 32 + (lane >> 2);
    const int cb = bn + wn * 64 + (lane & 3) * 2;
#pragma unroll
    for (int tm = 0; tm < 2; tm++)
#pragma unroll
        for (int tn = 0; tn < 8; tn++) {
            float* p0 = C + (size_t)(r0 + tm * 16) * ldC + cb + tn * 8;
            float* p1 = p0 + 8 * (size_t)ldC;
            if (accum) {
                float2 d0 = *(float2*)p0;
                d0.x += acc[tm][tn][0]; d0.y += acc[tm][tn][1];
                *(float2*)p0 = d0;
                float2 d1 = *(float2*)p1;
                d1.x += acc[tm][tn][2]; d1.y += acc[tm][tn][3];
                *(float2*)p1 = d1;
            } else {
                *(float2*)p0 = make_float2(acc[tm][tn][0], acc[tm][tn][1]);
                *(float2*)p1 = make_float2(acc[tm][tn][2], acc[tm][tn][3]);
            }
        }
}

// ================= persistent scan kernel (3-buffer h pipeline) =================
#define SC_WPITCH 1032
#define SC_HPITCH 132
#define SC_WS_FLOATS (24 * SC_WPITCH)        // 24768
#define SC_HS_FLOATS (64 * SC_HPITCH)        // 8448
#define SCAN_SMEM_BYTES ((SC_WS_FLOATS + 3 * SC_HS_FLOATS) * 4)   // 200,448

__global__ __launch_bounds__(128) void scan_kernel(
    float* hA, float* hB,
    const float* __restrict__ GI, const float* __restrict__ GG,
    const float* __restrict__ Whh,
    const float* __restrict__ bih, const float* __restrict__ bhh)
{
    extern __shared__ float sm[];
    float* ws = sm;
    float* hs = sm + SC_WS_FLOATS;

    const int tid = threadIdx.x;
    const int w   = tid >> 5;
    const int l   = tid & 31;
    const int dl  = l & 1;
    const int bg  = l >> 1;
    const int dloc = w * 2 + dl;
    const int bd0 = blockIdx.x * 8;
    const int d   = bd0 + dloc;

    const uint32_t hs_sm = (uint32_t)__cvta_generic_to_shared(hs);

    // load weight slice once: 24 rows x 1024
    for (int i = tid; i < 6144; i += 128) {
        int row = i >> 8, g = i & 255;
        int gate = row >> 3, dd = row & 7;
        float4 v = *(const float4*)(Whh + (size_t)(gate * 1024 + bd0 + dd) * 1024 + g * 4);
        *(float4*)&ws[row * SC_WPITCH + g * 4] = v;
    }
    __syncthreads();

    const float bir = bih[d], biz = bih[1024 + d], bin = bih[2048 + d];
    const float bhr = bhh[d], bhz = bhh[1024 + d], bhn = bhh[2048 + d];

    for (int t = 0; t < T_; t++) {
        const float* h_in = (t & 1) ? hB : hA;
        float*       h_out = (t & 1) ? hA : hB;
        const float* gi_t = GI + (size_t)t * B_ * D3_;
        const float* gg_t = GG + (size_t)t * B_ * D_;

        auto stageh = [&](int buf, int k0) {
#pragma unroll
            for (int r = 0; r < 16; r++) {
                int i = tid + 128 * r;
                int row = i >> 5, g = i & 31;
                cpasync16(hs_sm + (uint32_t)(buf * SC_HS_FLOATS + row * SC_HPITCH + g * 4) * 4u,
                          h_in + (size_t)row * 1024 + k0 + g * 4);
            }
        };

        // prologue: stage chunks 0 and 1 (buffers free: barrier synced the step)
        stageh(0, 0);   cpcommit();
        stageh(1, 128); cpcommit();

        // prefetch epilogue operands
        float hp4[4], gir4[4], giz4[4], gin4[4], G4[4];
#pragma unroll
        for (int i = 0; i < 4; i++) {
            int b = bg + 16 * i;
            hp4[i]  = h_in[b * 1024 + d];
            gir4[i] = gi_t[b * 3072 + d];
            giz4[i] = gi_t[b * 3072 + 1024 + d];
            gin4[i] = gi_t[b * 3072 + 2048 + d];
            G4[i]   = gg_t[b * 1024 + d];
        }

        ull accx[12], accy[12];
#pragma unroll
        for (int i = 0; i < 12; i++) { accx[i] = 0ull; accy[i] = 0ull; }

        for (int ch = 0; ch < 8; ch++) {
            if (ch + 2 < 8) {
                if (ch >= 1) __syncthreads();    // buffer (ch+2)%3 fully consumed?
                stageh((ch + 2) % 3, (ch + 2) * 128);
                cpcommit();
            }
            if (ch < 6) cpwait2(); else if (ch == 6) cpwait1(); else cpwait0();
            __syncthreads();

            const float* hb = hs + (ch % 3) * SC_HS_FLOATS;
            const float* hp0 = hb + (bg +  0) * SC_HPITCH;
            const float* hp1 = hb + (bg + 16) * SC_HPITCH;
            const float* hp2 = hb + (bg + 32) * SC_HPITCH;
            const float* hp3 = hb + (bg + 48) * SC_HPITCH;
            const float* wp0 = ws + (0 * 8 + dloc) * SC_WPITCH + ch * 128;
            const float* wp1 = ws + (1 * 8 + dloc) * SC_WPITCH + ch * 128;
            const float* wp2 = ws + (2 * 8 + dloc) * SC_WPITCH + ch * 128;

#pragma unroll 8
            for (int kk = 0; kk < 128; kk += 4) {
                ulonglong2 wv0 = *(const ulonglong2*)(wp0 + kk);
                ulonglong2 wv1 = *(const ulonglong2*)(wp1 + kk);
                ulonglong2 wv2 = *(const ulonglong2*)(wp2 + kk);
                ulonglong2 h0 = *(const ulonglong2*)(hp0 + kk);
                ulonglong2 h1 = *(const ulonglong2*)(hp1 + kk);
                ulonglong2 h2 = *(const ulonglong2*)(hp2 + kk);
                ulonglong2 h3 = *(const ulonglong2*)(hp3 + kk);
                ffma2(accx[0],  h0.x, wv0.x); ffma2(accx[1],  h0.x, wv1.x); ffma2(accx[2],  h0.x, wv2.x);
                ffma2(accx[3],  h1.x, wv0.x); ffma2(accx[4],  h1.x, wv1.x); ffma2(accx[5],  h1.x, wv2.x);
                ffma2(accx[6],  h2.x, wv0.x); ffma2(accx[7],  h2.x, wv1.x); ffma2(accx[8],  h2.x, wv2.x);
                ffma2(accx[9],  h3.x, wv0.x); ffma2(accx[10], h3.x, wv1.x); ffma2(accx[11], h3.x, wv2.x);
                ffma2(accy[0],  h0.y, wv0.y); ffma2(accy[1],  h0.y, wv1.y); ffma2(accy[2],  h0.y, wv2.y);
                ffma2(accy[3],  h1.y, wv0.y); ffma2(accy[4],  h1.y, wv1.y); ffma2(accy[5],  h1.y, wv2.y);
                ffma2(accy[6],  h2.y, wv0.y); ffma2(accy[7],  h2.y, wv1.y); ffma2(accy[8],  h2.y, wv2.y);
                ffma2(accy[9],  h3.y, wv0.y); ffma2(accy[10], h3.y, wv1.y); ffma2(accy[11], h3.y, wv2.y);
            }
        }

        // epilogue
#pragma unroll
        for (int i = 0; i < 4; i++) {
            int b = bg + 16 * i;
            float dr = sum2(accx[i*3+0]) + sum2(accy[i*3+0]);
            float dz = sum2(accx[i*3+1]) + sum2(accy[i*3+1]);
            float dn = sum2(accx[i*3+2]) + sum2(accy[i*3+2]);
            float r = sigf(gir4[i] + bir + dr + bhr);
            float z = sigf(giz4[i] + biz + dz + bhz);
            float n = tanhfast(gin4[i] + bin + r * (dn + bhn));
            float hatt = (1.f - z) * n + z * hp4[i];
            h_out[b * 1024 + d] = G4[i] * hatt + (1.f - G4[i]) * hp4[i];
        }

        // grid barrier (monotonic counter; all 128 CTAs resident)
        __syncthreads();
        __threadfence();
        if (tid == 0) {
            atomicAdd(&g_barrier, 1);
            volatile int* bp = &g_barrier;
            int target = 128 * (t + 1);
            while (*bp < target) __nanosleep(32);
        }
        __syncthreads();
        __threadfence();
    }
}

__global__ void reset_barrier_kernel() { g_barrier = 0; }

// ---------------- small M=64 split-K GEMM: C += A[64,K] @ W[N,K]^T ----------------
__global__ __launch_bounds__(256) void sgemm64_kernel(
    const float* __restrict__ A, int ldA,
    const float* __restrict__ W, int ldW,
    float* __restrict__ C, int ldC)
{
    __shared__ float As[16][68];
    __shared__ float Ws[16][68];
    const int tid = threadIdx.x;
    const int bn = blockIdx.x * 64;
    const int k0 = blockIdx.y * 256;
    const int tx = tid & 15, ty = tid >> 4;
    const int m0 = ty * 4, n0 = tx * 4;
    const int lrow = tid >> 2, lk = (tid & 3) * 4;

    ull acc[2][4];
#pragma unroll
    for (int i = 0; i < 2; i++)
#pragma unroll
        for (int j = 0; j < 4; j++) acc[i][j] = 0ull;

    for (int kc = 0; kc < 256; kc += 16) {
        float4 av = *(const float4*)(A + (size_t)lrow * ldA + k0 + kc + lk);
        float4 wv = *(const float4*)(W + (size_t)(bn + lrow) * ldW + k0 + kc + lk);
        __syncthreads();
        As[lk+0][lrow] = av.x; As[lk+1][lrow] = av.y; As[lk+2][lrow] = av.z; As[lk+3][lrow] = av.w;
        Ws[lk+0][lrow] = wv.x; Ws[lk+1][lrow] = wv.y; Ws[lk+2][lrow] = wv.z; Ws[lk+3][lrow] = wv.w;
        __syncthreads();
#pragma unroll
        for (int kk = 0; kk < 16; kk++) {
            ull a01 = *(const ull*)&As[kk][m0];
            ull a23 = *(const ull*)&As[kk][m0 + 2];
            float4 w4 = *(const float4*)&Ws[kk][n0];
            ull w0 = pk(w4.x, w4.x), w1 = pk(w4.y, w4.y);
            ull w2 = pk(w4.z, w4.z), w3 = pk(w4.w, w4.w);
            ffma2(acc[0][0], a01, w0); ffma2(acc[0][1], a01, w1);
            ffma2(acc[0][2], a01, w2); ffma2(acc[0][3], a01, w3);
            ffma2(acc[1][0], a23, w0); ffma2(acc[1][1], a23, w1);
            ffma2(acc[1][2], a23, w2); ffma2(acc[1][3], a23, w3);
        }
    }
#pragma unroll
    for (int j = 0; j < 4; j++) {
        float2 v0 = upk(acc[0][j]);
        float2 v1 = upk(acc[1][j]);
        atomicAdd(&C[(size_t)(m0 + 0) * ldC + bn + n0 + j], v0.x);
        atomicAdd(&C[(size_t)(m0 + 1) * ldC + bn + n0 + j], v0.y);
        atomicAdd(&C[(size_t)(m0 + 2) * ldC + bn + n0 + j], v1.x);
        atomicAdd(&C[(size_t)(m0 + 3) * ldC + bn + n0 + j], v1.y);
    }
}

// ---------------- elementwise kernels ----------------
__global__ void split_kernel(const float* __restrict__ s, __nv_bfloat16* __restrict__ hi,
                             __nv_bfloat16* __restrict__ lo, int n4)
{
    int i = blockIdx.x * 256 + threadIdx.x;
    if (i >= n4) return;
    float4 v = ((const float4*)s)[i];
    bsplit4(hi, lo, i, v.x, v.y, v.z, v.w);
}

__global__ void feat3b_kernel(const float* __restrict__ c, const float* __restrict__ x,
                              const float* __restrict__ y,
                              __nv_bfloat16* __restrict__ FAh, __nv_bfloat16* __restrict__ FAl,
                              __nv_bfloat16* __restrict__ FBh, __nv_bfloat16* __restrict__ FBl,
                              __nv_bfloat16* __restrict__ FCh, __nv_bfloat16* __restrict__ FCl)
{
    int i = blockIdx.x * 256 + threadIdx.x;
    int bc = ((i >> 8) & 63) * 256 + (i & 255);
    float4 cv = ((const float4*)c)[i];
    float4 xv = ((const float4*)x)[bc];
    float4 yv = ((const float4*)y)[bc];
    bsplit4(FAh, FAl, i, cv.x*xv.x, cv.y*xv.y, cv.z*xv.z, cv.w*xv.w);
    bsplit4(FBh, FBl, i, fabsf(cv.x-xv.x), fabsf(cv.y-xv.y), fabsf(cv.z-xv.z), fabsf(cv.w-xv.w));
    bsplit4(FCh, FCl, i, cv.x*yv.x, cv.y*yv.y, cv.z*yv.z, cv.w*yv.w);
}

__global__ void addrow_kernel(const float* __restrict__ S0, const float* __restrict__ rc,
                              float* __restrict__ S)
{
    int i = blockIdx.x * 256 + threadIdx.x;
    int bc = ((i >> 8) & 63) * 256 + (i & 255);
    float4 a = ((const float4*)S0)[i];
    float4 r = ((const float4*)rc)[bc];
    ((float4*)S)[i] = make_float4(a.x+r.x, a.y+r.y, a.z+r.z, a.w+r.w);
}

__global__ void tanhsplit_kernel(const float* __restrict__ S,
                                 __nv_bfloat16* __restrict__ hi, __nv_bfloat16* __restrict__ lo)
{
    int i = blockIdx.x * 256 + threadIdx.x;
    float4 v = ((const float4*)S)[i];
    bsplit4(hi, lo, i, tanhfast(v.x), tanhfast(v.y), tanhfast(v.z), tanhfast(v.w));
}

__global__ void sigbias_kernel(float* __restrict__ G, const float* __restrict__ bias)
{
    int i = blockIdx.x * 256 + threadIdx.x;
    float4 b = ((const float4*)bias)[i & 255];
    float4 v = ((float4*)G)[i];
    ((float4*)G)[i] = make_float4(sigf(v.x+b.x), sigf(v.y+b.y), sigf(v.z+b.z), sigf(v.w+b.w));
}

__global__ void rowbias2_kernel(float* __restrict__ rc, const float* __restrict__ rcq,
                                const float* __restrict__ bias)
{
    int i = blockIdx.x * 256 + threadIdx.x;
    float4 b = ((const float4*)bias)[i & 255];
    float4 v = ((float4*)rc)[i];
    float4 u = ((const float4*)rcq)[i];
    ((float4*)rc)[i] = make_float4(v.x+u.x+b.x, v.y+u.y+b.y, v.z+u.z+b.z, v.w+u.w+b.w);
}

__global__ void zero_kernel(float* __restrict__ p, int n4)
{
    int i = blockIdx.x * 256 + threadIdx.x;
    if (i < n4) ((float4*)p)[i] = make_float4(0.f, 0.f, 0.f, 0.f);
}

__global__ void gruew_kernel(const float* __restrict__ gi, const float* __restrict__ gh,
                             const float* __restrict__ h,  const float* __restrict__ bih,
                             const float* __restrict__ bhh, float* __restrict__ out)
{
    int i = blockIdx.x * 256 + threadIdx.x;
    int b = i >> 10, d = i & 1023;
    float gir = gi[b*3072 + d]        + bih[d];
    float giz = gi[b*3072 + 1024 + d] + bih[1024 + d];
    float gin = gi[b*3072 + 2048 + d] + bih[2048 + d];
    float ghr = gh[b*3072 + d]        + bhh[d];
    float ghz = gh[b*3072 + 1024 + d] + bhh[1024 + d];
    float ghn = gh[b*3072 + 2048 + d] + bhh[2048 + d];
    float r = sigf(gir + ghr);
    float z = sigf(giz + ghz);
    float n = tanhfast(gin + r * ghn);
    out[i] = (1.f - z) * n + z * h[i];
}

// ---------------- host orchestration ----------------
static void tgemm1(const __nv_bfloat16* Ah, const __nv_bfloat16* Al,
                   const __nv_bfloat16* Bh, const __nv_bfloat16* Bl,
                   int ldB, int kofs, float* C, int ldC, int N, int accum)
{
    TGSegs s{};
    s.Ah[0] = Ah; s.Al[0] = Al; s.kofs[0] = kofs; s.nseg = 1;
    dim3 g(N / 128, TB_ / 128);
    tgemm_kernel<<<g, 256, TGS_SMEM>>>(s, Bh, Bl, ldB, C, ldC, accum);
}

static void sgemm64(const float* A, int ldA, const float* W, int ldW,
                    float* C, int ldC, int N)
{
    dim3 g(N / 64, 4);
    sgemm64_kernel<<<g, 256>>>(A, ldA, W, ldW, C, ldC);
}

extern "C" void kernel_launch(void* const* d_in, const int* in_sizes, int n_in,
                              void* d_out, int out_size)
{
    const float* c    = (const float*)d_in[0];
    const float* q    = (const float*)d_in[1];
    const float* Wb   = (const float*)d_in[2];
    const float* W1   = (const float*)d_in[3];
    const float* W1b  = (const float*)d_in[4];
    const float* W2   = (const float*)d_in[5];
    const float* W2b  = (const float*)d_in[6];
    const float* mWih = (const float*)d_in[7];
    const float* mWhh = (const float*)d_in[8];
    const float* mbih = (const float*)d_in[9];
    const float* mbhh = (const float*)d_in[10];
    const float* aWih = (const float*)d_in[11];
    const float* aWhh = (const float*)d_in[12];
    const float* abih = (const float*)d_in[13];
    const float* abhh = (const float*)d_in[14];

    cudaFuncSetAttribute(tgemm_kernel, cudaFuncAttributeMaxDynamicSharedMemorySize, TGS_SMEM);
    cudaFuncSetAttribute(scan_kernel,  cudaFuncAttributeMaxDynamicSharedMemorySize, SCAN_SMEM_BYTES);

    float *pG, *pSinv, *pS, *pGI, *pWbq, *pWbm, *prc, *prcq;
    float *ph0, *ph1, *pm, *pm2, *pgi, *pgh;
    __nv_bfloat16 *bAh, *bAl, *FAh, *FAl, *FBh, *FBl, *FCh, *FCl;
    __nv_bfloat16 *bW1h, *bW1l, *bW2h, *bW2l, *bWihh, *bWihl;
    cudaGetSymbolAddress((void**)&pG,    g_FAg);
    cudaGetSymbolAddress((void**)&pSinv, g_Sinv);
    cudaGetSymbolAddress((void**)&pS,    g_S);
    cudaGetSymbolAddress((void**)&pGI,   g_GI);
    cudaGetSymbolAddress((void**)&pWbq,  g_Wbq);
    cudaGetSymbolAddress((void**)&pWbm,  g_Wbm);
    cudaGetSymbolAddress((void**)&prc,   g_rc);
    cudaGetSymbolAddress((void**)&prcq,  g_rcq);
    cudaGetSymbolAddress((void**)&ph0,   g_h0);
    cudaGetSymbolAddress((void**)&ph1,   g_h1);
    cudaGetSymbolAddress((void**)&pm,    g_m);
    cudaGetSymbolAddress((void**)&pm2,   g_m2);
    cudaGetSymbolAddress((void**)&pgi,   g_gi);
    cudaGetSymbolAddress((void**)&pgh,   g_gh);
    cudaGetSymbolAddress((void**)&bAh,   g_bAh);
    cudaGetSymbolAddress((void**)&bAl,   g_bAl);
    cudaGetSymbolAddress((void**)&FAh,   g_FAh);
    cudaGetSymbolAddress((void**)&FAl,   g_FAl);
    cudaGetSymbolAddress((void**)&FBh,   g_FBh);
    cudaGetSymbolAddress((void**)&FBl,   g_FBl);
    cudaGetSymbolAddress((void**)&FCh,   g_FCh);
    cudaGetSymbolAddress((void**)&FCl,   g_FCl);
    cudaGetSymbolAddress((void**)&bW1h,  g_W1h);
    cudaGetSymbolAddress((void**)&bW1l,  g_W1l);
    cudaGetSymbolAddress((void**)&bW2h,  g_W2h);
    cudaGetSymbolAddress((void**)&bW2l,  g_W2l);
    cudaGetSymbolAddress((void**)&bWihh, g_Wihh);
    cudaGetSymbolAddress((void**)&bWihl, g_Wihl);

    const int GRID_TBD4 = (TB_ * D_ / 4) / 256;
    const int BD4  = B_ * D_ / 4;
    const int BD34 = B_ * D3_ / 4;
    const int GRID_BD4  = BD4 / 256;
    const int GRID_BD34 = BD34 / 256;
    const int GRID_BD   = (B_ * D_) / 256;

    cudaMemcpyAsync(pm, q, (size_t)B_ * D_ * sizeof(float), cudaMemcpyDeviceToDevice);

    // weight splits
    split_kernel<<<(D_*D9_/4)/256, 256>>>(W1, bW1h, bW1l, D_*D9_/4);
    split_kernel<<<(D_*D_/4)/256, 256>>>(W2, bW2h, bW2l, D_*D_/4);
    split_kernel<<<(D3_*D_/4)/256, 256>>>(aWih, bWihh, bWihl, D3_*D_/4);

    // episode-invariant precompute
    zero_kernel<<<GRID_BD4, 256>>>(pWbq, BD4);
    sgemm64(q, D_, Wb, D_, pWbq, D_, D_);
    zero_kernel<<<GRID_BD4, 256>>>(prcq, BD4);
    sgemm64(q, D_, W1 + 2*D_, D9_, prcq, D_, D_);

    feat3b_kernel<<<GRID_TBD4, 256>>>(c, q, pWbq, FAh, FAl, FBh, FBl, FCh, FCl);
    split_kernel<<<GRID_TBD4, 256>>>(c, bAh, bAl, TB_*D_/4);

    // Sinv = c@V0 + cq@V3 + |c-q|@V5 + cWbq@V7  (single fused-K launch)
    {
        TGSegs s{};
        s.Ah[0] = bAh; s.Al[0] = bAl; s.kofs[0] = 0*D_;
        s.Ah[1] = FAh; s.Al[1] = FAl; s.kofs[1] = 3*D_;
        s.Ah[2] = FBh; s.Al[2] = FBl; s.kofs[2] = 5*D_;
        s.Ah[3] = FCh; s.Al[3] = FCl; s.kofs[3] = 7*D_;
        s.nseg = 4;
        dim3 g(D_ / 128, TB_ / 128);
        tgemm_kernel<<<g, 256, TGS_SMEM>>>(s, bW1h, bW1l, D9_, pSinv, D_, 0);
    }
    tgemm1(bAh, bAl, bWihh, bWihl, D_, 0, pGI, D3_, D3_, 0);    // gi_att all t

    float* mc = pm;
    float* mn = pm2;
    for (int ep = 0; ep < 2; ep++) {
        zero_kernel<<<GRID_BD4, 256>>>(pWbm, BD4);
        sgemm64(mc, D_, Wb, D_, pWbm, D_, D_);
        zero_kernel<<<GRID_BD4, 256>>>(prc, BD4);
        sgemm64(mc, D_, W1 + 1*D_, D9_, prc, D_, D_);
        rowbias2_kernel<<<GRID_BD4, 256>>>(prc, prcq, W1b);

        feat3b_kernel<<<GRID_TBD4, 256>>>(c, mc, pWbm, FAh, FAl, FBh, FBl, FCh, FCl);
        addrow_kernel<<<GRID_TBD4, 256>>>(pSinv, prc, pS);

        // S += cm@V4 + |c-m|@V6 + cWbm@V8  (single fused-K launch)
        {
            TGSegs s{};
            s.Ah[0] = FAh; s.Al[0] = FAl; s.kofs[0] = 4*D_;
            s.Ah[1] = FBh; s.Al[1] = FBl; s.kofs[1] = 6*D_;
            s.Ah[2] = FCh; s.Al[2] = FCl; s.kofs[2] = 8*D_;
            s.nseg = 3;
            dim3 g(D_ / 128, TB_ / 128);
            tgemm_kernel<<<g, 256, TGS_SMEM>>>(s, bW1h, bW1l, D9_, pS, D_, 1);
        }

        tanhsplit_kernel<<<GRID_TBD4, 256>>>(pS, bAh, bAl);
        tgemm1(bAh, bAl, bW2h, bW2l, D_, 0, pG, D_, D_, 0);
        sigbias_kernel<<<GRID_TBD4, 256>>>(pG, W2b);

        zero_kernel<<<GRID_BD4, 256>>>(ph0, BD4);
        reset_barrier_kernel<<<1, 1>>>();
        scan_kernel<<<128, 128, SCAN_SMEM_BYTES>>>(ph0, ph1, pGI, pG, aWhh, abih, abhh);

        zero_kernel<<<GRID_BD34, 256>>>(pgi, BD34);
        sgemm64(ph0, D_, mWih, D_, pgi, D3_, D3_);
        zero_kernel<<<GRID_BD34, 256>>>(pgh, BD34);
        sgemm64(mc, D_, mWhh, D_, pgh, D3_, D3_);
        gruew_kernel<<<GRID_BD, 256>>>(pgi, pgh, mc, mbih, mbhh, mn);
        float* tmp = mc; mc = mn; mn = tmp;
    }

    cudaMemcpyAsync(d_out, mc, (size_t)B_ * D_ * sizeof(float), cudaMemcpyDeviceToDevice);
}

// round 16
// speedup vs baseline: 1.2436x; 1.2436x over previous
#include <cuda_runtime.h>
#include <cuda_bf16.h>
#include <stdint.h>

#define T_  128
#define B_  64
#define D_  1024
#define TB_ (T_*B_)
#define D3_ (3*D_)
#define D9_ (9*D_)

typedef unsigned long long ull;

// ---------------- static scratch (no allocation anywhere) ----------------
__device__ float g_FAg[TB_*D_];
__device__ float g_Sinv[TB_*D_];
__device__ float g_S[TB_*D_];
__device__ float g_GI[TB_*D3_];
__device__ float g_Wbq[B_*D_];
__device__ float g_Wbm[B_*D_];
__device__ float g_rc[B_*D_];
__device__ float g_rcq[B_*D_];
__device__ float g_h0[B_*D_];
__device__ float g_h1[B_*D_];
__device__ float g_m[B_*D_];
__device__ float g_m2[B_*D_];
__device__ float g_gi[B_*D3_];
__device__ float g_gh[B_*D3_];
__device__ int   g_barrier;

// bf16 split buffers
__device__ __nv_bfloat16 g_bAh[TB_*D_];
__device__ __nv_bfloat16 g_bAl[TB_*D_];
__device__ __nv_bfloat16 g_FAh[TB_*D_];
__device__ __nv_bfloat16 g_FAl[TB_*D_];
__device__ __nv_bfloat16 g_FBh[TB_*D_];
__device__ __nv_bfloat16 g_FBl[TB_*D_];
__device__ __nv_bfloat16 g_FCh[TB_*D_];
__device__ __nv_bfloat16 g_FCl[TB_*D_];
__device__ __nv_bfloat16 g_W1h[D_*D9_];
__device__ __nv_bfloat16 g_W1l[D_*D9_];
__device__ __nv_bfloat16 g_W2h[D_*D_];
__device__ __nv_bfloat16 g_W2l[D_*D_];
__device__ __nv_bfloat16 g_Wihh[D3_*D_];
__device__ __nv_bfloat16 g_Wihl[D3_*D_];
__device__ __nv_bfloat16 g_Whhh[D3_*D_];
__device__ __nv_bfloat16 g_Whhl[D3_*D_];
// h as bf16 hi/lo (ping-pong) for the tensor-core scan
__device__ __nv_bfloat16 g_hAbh[B_*D_];
__device__ __nv_bfloat16 g_hAbl[B_*D_];
__device__ __nv_bfloat16 g_hBbh[B_*D_];
__device__ __nv_bfloat16 g_hBbl[B_*D_];

// ---------------- helpers ----------------
__device__ __forceinline__ void ffma2(ull& c, ull a, ull b) {
    asm("fma.rn.f32x2 %0, %1, %2, %0;" : "+l"(c) : "l"(a), "l"(b));
}
__device__ __forceinline__ ull pk(float lo, float hi) {
    ull r; asm("mov.b64 %0, {%1, %2};" : "=l"(r) : "f"(lo), "f"(hi)); return r;
}
__device__ __forceinline__ float2 upk(ull a) {
    float2 v; asm("mov.b64 {%0, %1}, %2;" : "=f"(v.x), "=f"(v.y) : "l"(a)); return v;
}
__device__ __forceinline__ float sigf(float x)     { return 1.f / (1.f + __expf(-x)); }
__device__ __forceinline__ float tanhfast(float x) { return 2.f / (1.f + __expf(-2.f*x)) - 1.f; }

__device__ __forceinline__ void cpasync16(uint32_t dst, const void* src) {
    asm volatile("cp.async.cg.shared.global [%0], [%1], 16;" :: "r"(dst), "l"(src));
}
__device__ __forceinline__ void cpcommit() { asm volatile("cp.async.commit_group;"); }
__device__ __forceinline__ void cpwait1()  { asm volatile("cp.async.wait_group 1;"); }
__device__ __forceinline__ void cpwait0()  { asm volatile("cp.async.wait_group 0;"); }

__device__ __forceinline__ void ldmx4(uint32_t addr, uint32_t* r) {
    asm volatile("ldmatrix.sync.aligned.m8n8.x4.shared.b16 {%0,%1,%2,%3}, [%4];"
                 : "=r"(r[0]), "=r"(r[1]), "=r"(r[2]), "=r"(r[3]) : "r"(addr));
}
__device__ __forceinline__ void ldmx2(uint32_t addr, uint32_t* r) {
    asm volatile("ldmatrix.sync.aligned.m8n8.x2.shared.b16 {%0,%1}, [%2];"
                 : "=r"(r[0]), "=r"(r[1]) : "r"(addr));
}

#define MMA_BF16(c, a, b0, b1) \
    asm volatile("mma.sync.aligned.m16n8k16.row.col.f32.bf16.bf16.f32 " \
                 "{%0,%1,%2,%3}, {%4,%5,%6,%7}, {%8,%9}, {%0,%1,%2,%3};" \
                 : "+f"((c)[0]), "+f"((c)[1]), "+f"((c)[2]), "+f"((c)[3]) \
                 : "r"((a)[0]), "r"((a)[1]), "r"((a)[2]), "r"((a)[3]), \
                   "r"(b0), "r"(b1))

__device__ __forceinline__ void bsplit4(__nv_bfloat16* hi, __nv_bfloat16* lo, int i,
                                        float x, float y, float z, float w)
{
    __nv_bfloat16 hx = __float2bfloat16(x), hy = __float2bfloat16(y);
    __nv_bfloat16 hz = __float2bfloat16(z), hw = __float2bfloat16(w);
    ((__nv_bfloat162*)hi)[2*i]   = __nv_bfloat162(hx, hy);
    ((__nv_bfloat162*)hi)[2*i+1] = __nv_bfloat162(hz, hw);
    ((__nv_bfloat162*)lo)[2*i]   = __nv_bfloat162(__float2bfloat16(x - __bfloat162float(hx)),
                                                  __float2bfloat16(y - __bfloat162float(hy)));
    ((__nv_bfloat162*)lo)[2*i+1] = __nv_bfloat162(__float2bfloat16(z - __bfloat162float(hz)),
                                                  __float2bfloat16(w - __bfloat162float(hw)));
}

// ================= mma.sync split-bf16 GEMM (R14-exact, proven) =================
#define KC      32
#define PITCHB  80u
#define TILE_B  (128u * PITCHB)
#define BUF_B   (4u * TILE_B)
#define TGS_SMEM (2 * BUF_B)

__global__ __launch_bounds__(256) void tgemm_kernel(
    const __nv_bfloat16* __restrict__ Ah, const __nv_bfloat16* __restrict__ Al,
    const __nv_bfloat16* __restrict__ Bh, const __nv_bfloat16* __restrict__ Bl,
    int ldB, int kofs,
    float* __restrict__ C, int ldC, int accum)
{
    extern __shared__ __align__(16) char smraw[];
    const uint32_t sb = (uint32_t)__cvta_generic_to_shared(smraw);

    const int tid  = threadIdx.x;
    const int wid  = tid >> 5;
    const int lane = tid & 31;
    const int bm   = blockIdx.y * 128;
    const int bn   = blockIdx.x * 128;
    const int wm   = wid & 3;
    const int wn   = wid >> 2;

    float acc[2][8][4];
#pragma unroll
    for (int i = 0; i < 2; i++)
#pragma unroll
        for (int j = 0; j < 8; j++)
#pragma unroll
            for (int k = 0; k < 4; k++) acc[i][j][k] = 0.f;

    auto stage = [&](int buf, int k0) {
        uint32_t base = sb + (uint32_t)buf * BUF_B;
#pragma unroll
        for (int r = 0; r < 8; r++) {
            int id   = tid + 256 * r;
            int tile = id >> 9;
            int row  = (id >> 2) & 127;
            int g    = id & 3;
            uint32_t daddr = base + (uint32_t)tile * TILE_B + (uint32_t)row * PITCHB + (uint32_t)g * 16u;
            const __nv_bfloat16* src;
            if      (tile == 0) src = Ah + (size_t)(bm + row) * 1024 + k0 + g * 8;
            else if (tile == 1) src = Al + (size_t)(bm + row) * 1024 + k0 + g * 8;
            else if (tile == 2) src = Bh + (size_t)(bn + row) * ldB + kofs + k0 + g * 8;
            else                src = Bl + (size_t)(bn + row) * ldB + kofs + k0 + g * 8;
            cpasync16(daddr, src);
        }
    };

    stage(0, 0); cpcommit();

    for (int ch = 0; ch < 1024 / KC; ch++) {
        if (ch + 1 < 1024 / KC) { stage((ch + 1) & 1, (ch + 1) * KC); cpcommit(); cpwait1(); }
        else                    { cpwait0(); }
        __syncthreads();

        uint32_t base = sb + (uint32_t)(ch & 1) * BUF_B;
#pragma unroll
        for (int ks = 0; ks < 2; ks++) {
            uint32_t ah[2][4], al[2][4], bh[4][4], bl[4][4];
#pragma unroll
            for (int tm = 0; tm < 2; tm++) {
                uint32_t row = (uint32_t)(wm * 32 + tm * 16 + (lane & 15));
                uint32_t addr = base + row * PITCHB + (uint32_t)(ks * 32) + (uint32_t)((lane >> 4) * 16);
                ldmx4(addr, ah[tm]);
                ldmx4(addr + TILE_B, al[tm]);
            }
#pragma unroll
            for (int tb = 0; tb < 4; tb++) {
                uint32_t rn = (uint32_t)(wn * 64 + tb * 16 + ((lane >> 4) << 3) + (lane & 7));
                uint32_t addr = base + 2u * TILE_B + rn * PITCHB + (uint32_t)(ks * 32) + (uint32_t)(((lane >> 3) & 1) * 16);
                ldmx4(addr, bh[tb]);
                ldmx4(addr + TILE_B, bl[tb]);
            }
#pragma unroll
            for (int tm = 0; tm < 2; tm++)
#pragma unroll
                for (int tn = 0; tn < 8; tn++) {
                    int tb = tn >> 1, s = (tn & 1) * 2;
                    MMA_BF16(acc[tm][tn], ah[tm], bh[tb][s], bh[tb][s + 1]);
                    MMA_BF16(acc[tm][tn], ah[tm], bl[tb][s], bl[tb][s + 1]);
                    MMA_BF16(acc[tm][tn], al[tm], bh[tb][s], bh[tb][s + 1]);
                }
        }
        __syncthreads();
    }

    const int r0 = bm + wm * 32 + (lane >> 2);
    const int cb = bn + wn * 64 + (lane & 3) * 2;
#pragma unroll
    for (int tm = 0; tm < 2; tm++)
#pragma unroll
        for (int tn = 0; tn < 8; tn++) {
            float* p0 = C + (size_t)(r0 + tm * 16) * ldC + cb + tn * 8;
            float* p1 = p0 + 8 * (size_t)ldC;
            if (accum) {
                float2 d0 = *(float2*)p0;
                d0.x += acc[tm][tn][0]; d0.y += acc[tm][tn][1];
                *(float2*)p0 = d0;
                float2 d1 = *(float2*)p1;
                d1.x += acc[tm][tn][2]; d1.y += acc[tm][tn][3];
                *(float2*)p1 = d1;
            } else {
                *(float2*)p0 = make_float2(acc[tm][tn][0], acc[tm][tn][1]);
                *(float2*)p1 = make_float2(acc[tm][tn][2], acc[tm][tn][3]);
            }
        }
}

// ================= persistent scan kernel v4: tensor-core recurrent GEMM =================
// 128 blocks x 128 threads. Block owns d-cols [blk*8, blk*8+8).
// Whh slice (24 rows x 1024, bf16 hi+lo) staged into smem ONCE, tiled for ldmatrix.
// h carried as fp32 + bf16 hi/lo; per step each block computes [64 b x 24 n] via
// mma.sync split-bf16 (hh + hl + lh). Warp w -> b rows 16w..16w+15, all 3 n-tiles.
#define SCW_PER 1920u                      // 24 rows * 80 B, one (chunk,sub,op) tile
#define SCW_BYTES (8u*4u*2u*SCW_PER)       // 122,880
#define SCH_PER 5120u                      // 64 rows * 80 B
#define SCH_BUF (4u*2u*SCH_PER)            // 40,960 per buffer
#define SCAN_SMEM_BYTES (SCW_BYTES + 2u*SCH_BUF)   // 204,800

__device__ __forceinline__ uint32_t WT(int chunk, int sub, int op, int row) {
    return (uint32_t)(((chunk*4 + sub)*2 + op)) * SCW_PER + (uint32_t)row * 80u;
}
__device__ __forceinline__ uint32_t HT(int buf, int sub, int op, int row) {
    return SCW_BYTES + (uint32_t)buf * SCH_BUF + (uint32_t)((sub*2 + op)) * SCH_PER + (uint32_t)row * 80u;
}

__global__ __launch_bounds__(128) void scan_kernel(
    float* hA, float* hB,
    __nv_bfloat16* hAbh, __nv_bfloat16* hAbl,
    __nv_bfloat16* hBbh, __nv_bfloat16* hBbl,
    const float* __restrict__ GI, const float* __restrict__ GG,
    const __nv_bfloat16* __restrict__ Whhh, const __nv_bfloat16* __restrict__ Whhl,
    const float* __restrict__ bih, const float* __restrict__ bhh)
{
    extern __shared__ __align__(16) char smraw[];
    const uint32_t sb = (uint32_t)__cvta_generic_to_shared(smraw);

    const int tid  = threadIdx.x;
    const int w    = tid >> 5;
    const int lane = tid & 31;
    const int bd0  = blockIdx.x * 8;

    // ---- load Whh slice (hi+lo) once: 6144 16B-granules ----
    for (int i = tid; i < 6144; i += 128) {
        int op  = i / 3072;
        int rem = i - op * 3072;
        int row = rem >> 7;            // 0..23
        int g   = rem & 127;           // granule in row (8 bf16 each)
        int k   = g * 8;
        int chunk = k >> 7, kin = k & 127, sub = kin >> 5, kins = kin & 31;
        uint32_t dst = sb + WT(chunk, sub, op, row) + (uint32_t)((kins >> 3) * 16);
        int gate = row >> 3, dd = row & 7;
        const __nv_bfloat16* src = (op ? Whhl : Whhh) + (size_t)(gate * 1024 + bd0 + dd) * 1024 + k;
        cpasync16(dst, src);
    }
    cpcommit(); cpwait0();
    __syncthreads();

    // thread's (b, d) coverage: b0 = 16w + lane/4, b1 = b0+8; d0 = bd0+2*(lane&3), d1 = d0+1
    const int b0 = w * 16 + (lane >> 2);
    const int b1 = b0 + 8;
    const int d0 = bd0 + 2 * (lane & 3);
    const int d1 = d0 + 1;
    const float bir[2] = { bih[d0],        bih[d1] };
    const float biz[2] = { bih[1024 + d0], bih[1024 + d1] };
    const float bin[2] = { bih[2048 + d0], bih[2048 + d1] };
    const float bhr[2] = { bhh[d0],        bhh[d1] };
    const float bhz[2] = { bhh[1024 + d0], bhh[1024 + d1] };
    const float bhn[2] = { bhh[2048 + d0], bhh[2048 + d1] };

    for (int t = 0; t < T_; t++) {
        const float* hf_in = (t & 1) ? hB : hA;
        float*       hf_out = (t & 1) ? hA : hB;
        const __nv_bfloat16* hh_in = (t & 1) ? hBbh : hAbh;
        const __nv_bfloat16* hl_in = (t & 1) ? hBbl : hAbl;
        __nv_bfloat16* hh_out = (t & 1) ? hAbh : hBbh;
        __nv_bfloat16* hl_out = (t & 1) ? hAbl : hBbl;
        const float* gi_t = GI + (size_t)t * B_ * D3_;
        const float* gg_t = GG + (size_t)t * B_ * D_;

        auto stageh = [&](int buf, int k0) {
#pragma unroll
            for (int r = 0; r < 16; r++) {
                int id  = tid + 128 * r;       // 0..2047
                int op  = id >> 10;
                int row = (id >> 4) & 63;
                int g   = id & 15;
                int sub = g >> 2;
                uint32_t dst = sb + HT(buf, sub, op, row) + (uint32_t)((g & 3) * 16);
                const __nv_bfloat16* src = (op ? hl_in : hh_in) + (size_t)row * 1024 + k0 + g * 8;
                cpasync16(dst, src);
            }
        };

        stageh(0, 0); cpcommit();

        // prefetch epilogue operands (fp32)
        float hp[2][2], gir[2][2], giz[2][2], gin[2][2], G[2][2];
#pragma unroll
        for (int i = 0; i < 2; i++) {
            int b = i ? b1 : b0;
#pragma unroll
            for (int e = 0; e < 2; e++) {
                int d = e ? d1 : d0;
                hp[i][e]  = hf_in[b * 1024 + d];
                gir[i][e] = gi_t[b * 3072 + d];
                giz[i][e] = gi_t[b * 3072 + 1024 + d];
                gin[i][e] = gi_t[b * 3072 + 2048 + d];
                G[i][e]   = gg_t[b * 1024 + d];
            }
        }

        float acc[3][4];
#pragma unroll
        for (int n = 0; n < 3; n++)
#pragma unroll
            for (int k = 0; k < 4; k++) acc[n][k] = 0.f;

        for (int ch = 0; ch < 8; ch++) {
            if (ch < 7) { stageh((ch + 1) & 1, (ch + 1) * 128); cpcommit(); cpwait1(); }
            else        { cpwait0(); }
            __syncthreads();

            const int buf = ch & 1;
#pragma unroll
            for (int ks = 0; ks < 8; ks++) {
                const int sub = ks >> 1;
                const uint32_t kso = (uint32_t)((ks & 1) * 32);
                uint32_t ah[4], al[4], bh01[4], bl01[4], bh2[2], bl2[2];
                {
                    uint32_t arow = (uint32_t)(w * 16 + (lane & 15));
                    uint32_t a0 = sb + HT(buf, sub, 0, 0) + arow * 80u + kso + (uint32_t)((lane >> 4) * 16);
                    ldmx4(a0, ah);
                    ldmx4(a0 + SCH_PER, al);   // op=1 tile is +SCH_PER
                }
                {
                    uint32_t brow = (uint32_t)(((lane >> 4) << 3) + (lane & 7));
                    uint32_t koff = kso + (uint32_t)(((lane >> 3) & 1) * 16);
                    uint32_t bA = sb + WT(ch, sub, 0, 0) + brow * 80u + koff;
                    ldmx4(bA, bh01);
                    ldmx4(bA + SCW_PER, bl01);
                    uint32_t brow2 = (uint32_t)(16 + (lane & 7));
                    uint32_t bB = sb + WT(ch, sub, 0, 0) + brow2 * 80u + koff;
                    ldmx2(bB, bh2);
                    ldmx2(bB + SCW_PER, bl2);
                }
                MMA_BF16(acc[0], ah, bh01[0], bh01[1]);
                MMA_BF16(acc[0], ah, bl01[0], bl01[1]);
                MMA_BF16(acc[0], al, bh01[0], bh01[1]);
                MMA_BF16(acc[1], ah, bh01[2], bh01[3]);
                MMA_BF16(acc[1], ah, bl01[2], bl01[3]);
                MMA_BF16(acc[1], al, bh01[2], bh01[3]);
                MMA_BF16(acc[2], ah, bh2[0], bh2[1]);
                MMA_BF16(acc[2], ah, bl2[0], bl2[1]);
                MMA_BF16(acc[2], al, bh2[0], bh2[1]);
            }
            __syncthreads();
        }

        // epilogue: acc[gate][i*2+e] = dot for (b_i, d_e)
#pragma unroll
        for (int i = 0; i < 2; i++) {
            int b = i ? b1 : b0;
#pragma unroll
            for (int e = 0; e < 2; e++) {
                int d = e ? d1 : d0;
                float dr = acc[0][i * 2 + e];
                float dz = acc[1][i * 2 + e];
                float dn = acc[2][i * 2 + e];
                float r = sigf(gir[i][e] + bir[e] + dr + bhr[e]);
                float z = sigf(giz[i][e] + biz[e] + dz + bhz[e]);
                float n = tanhfast(gin[i][e] + bin[e] + r * (dn + bhn[e]));
                float hatt = (1.f - z) * n + z * hp[i][e];
                float hnew = G[i][e] * hatt + (1.f - G[i][e]) * hp[i][e];
                hf_out[b * 1024 + d] = hnew;
                __nv_bfloat16 hh = __float2bfloat16(hnew);
                hh_out[b * 1024 + d] = hh;
                hl_out[b * 1024 + d] = __float2bfloat16(hnew - __bfloat162float(hh));
            }
        }

        // grid barrier (monotonic counter; 128 CTAs all resident at 1 CTA/SM)
        __syncthreads();
        __threadfence();
        if (tid == 0) {
            atomicAdd(&g_barrier, 1);
            volatile int* bp = &g_barrier;
            int target = 128 * (t + 1);
            while (*bp < target) __nanosleep(32);
        }
        __syncthreads();
        __threadfence();
    }
}

__global__ void reset_barrier_kernel() { g_barrier = 0; }

// ---------------- small M=64 split-K GEMM (R14-exact) ----------------
__global__ __launch_bounds__(256) void sgemm64_kernel(
    const float* __restrict__ A, int ldA,
    const float* __restrict__ W, int ldW,
    float* __restrict__ C, int ldC)
{
    __shared__ float As[16][68];
    __shared__ float Ws[16][68];
    const int tid = threadIdx.x;
    const int bn = blockIdx.x * 64;
    const int k0 = blockIdx.y * 256;
    const int tx = tid & 15, ty = tid >> 4;
    const int m0 = ty * 4, n0 = tx * 4;
    const int lrow = tid >> 2, lk = (tid & 3) * 4;

    ull acc[2][4];
#pragma unroll
    for (int i = 0; i < 2; i++)
#pragma unroll
        for (int j = 0; j < 4; j++) acc[i][j] = 0ull;

    for (int kc = 0; kc < 256; kc += 16) {
        float4 av = *(const float4*)(A + (size_t)lrow * ldA + k0 + kc + lk);
        float4 wv = *(const float4*)(W + (size_t)(bn + lrow) * ldW + k0 + kc + lk);
        __syncthreads();
        As[lk+0][lrow] = av.x; As[lk+1][lrow] = av.y; As[lk+2][lrow] = av.z; As[lk+3][lrow] = av.w;
        Ws[lk+0][lrow] = wv.x; Ws[lk+1][lrow] = wv.y; Ws[lk+2][lrow] = wv.z; Ws[lk+3][lrow] = wv.w;
        __syncthreads();
#pragma unroll
        for (int kk = 0; kk < 16; kk++) {
            ull a01 = *(const ull*)&As[kk][m0];
            ull a23 = *(const ull*)&As[kk][m0 + 2];
            float4 w4 = *(const float4*)&Ws[kk][n0];
            ull w0 = pk(w4.x, w4.x), w1 = pk(w4.y, w4.y);
            ull w2 = pk(w4.z, w4.z), w3 = pk(w4.w, w4.w);
            ffma2(acc[0][0], a01, w0); ffma2(acc[0][1], a01, w1);
            ffma2(acc[0][2], a01, w2); ffma2(acc[0][3], a01, w3);
            ffma2(acc[1][0], a23, w0); ffma2(acc[1][1], a23, w1);
            ffma2(acc[1][2], a23, w2); ffma2(acc[1][3], a23, w3);
        }
    }
#pragma unroll
    for (int j = 0; j < 4; j++) {
        float2 v0 = upk(acc[0][j]);
        float2 v1 = upk(acc[1][j]);
        atomicAdd(&C[(size_t)(m0 + 0) * ldC + bn + n0 + j], v0.x);
        atomicAdd(&C[(size_t)(m0 + 1) * ldC + bn + n0 + j], v0.y);
        atomicAdd(&C[(size_t)(m0 + 2) * ldC + bn + n0 + j], v1.x);
        atomicAdd(&C[(size_t)(m0 + 3) * ldC + bn + n0 + j], v1.y);
    }
}

// ---------------- elementwise kernels ----------------
__global__ void split_kernel(const float* __restrict__ s, __nv_bfloat16* __restrict__ hi,
                             __nv_bfloat16* __restrict__ lo, int n4)
{
    int i = blockIdx.x * 256 + threadIdx.x;
    if (i >= n4) return;
    float4 v = ((const float4*)s)[i];
    bsplit4(hi, lo, i, v.x, v.y, v.z, v.w);
}

__global__ void feat3b_kernel(const float* __restrict__ c, const float* __restrict__ x,
                              const float* __restrict__ y,
                              __nv_bfloat16* __restrict__ FAh, __nv_bfloat16* __restrict__ FAl,
                              __nv_bfloat16* __restrict__ FBh, __nv_bfloat16* __restrict__ FBl,
                              __nv_bfloat16* __restrict__ FCh, __nv_bfloat16* __restrict__ FCl)
{
    int i = blockIdx.x * 256 + threadIdx.x;
    int bc = ((i >> 8) & 63) * 256 + (i & 255);
    float4 cv = ((const float4*)c)[i];
    float4 xv = ((const float4*)x)[bc];
    float4 yv = ((const float4*)y)[bc];
    bsplit4(FAh, FAl, i, cv.x*xv.x, cv.y*xv.y, cv.z*xv.z, cv.w*xv.w);
    bsplit4(FBh, FBl, i, fabsf(cv.x-xv.x), fabsf(cv.y-xv.y), fabsf(cv.z-xv.z), fabsf(cv.w-xv.w));
    bsplit4(FCh, FCl, i, cv.x*yv.x, cv.y*yv.y, cv.z*yv.z, cv.w*yv.w);
}

__global__ void addrow_kernel(const float* __restrict__ S0, const float* __restrict__ rc,
                              float* __restrict__ S)
{
    int i = blockIdx.x * 256 + threadIdx.x;
    int bc = ((i >> 8) & 63) * 256 + (i & 255);
    float4 a = ((const float4*)S0)[i];
    float4 r = ((const float4*)rc)[bc];
    ((float4*)S)[i] = make_float4(a.x+r.x, a.y+r.y, a.z+r.z, a.w+r.w);
}

__global__ void tanhsplit_kernel(const float* __restrict__ S,
                                 __nv_bfloat16* __restrict__ hi, __nv_bfloat16* __restrict__ lo)
{
    int i = blockIdx.x * 256 + threadIdx.x;
    float4 v = ((const float4*)S)[i];
    bsplit4(hi, lo, i, tanhfast(v.x), tanhfast(v.y), tanhfast(v.z), tanhfast(v.w));
}

__global__ void sigbias_kernel(float* __restrict__ G, const float* __restrict__ bias)
{
    int i = blockIdx.x * 256 + threadIdx.x;
    float4 b = ((const float4*)bias)[i & 255];
    float4 v = ((float4*)G)[i];
    ((float4*)G)[i] = make_float4(sigf(v.x+b.x), sigf(v.y+b.y), sigf(v.z+b.z), sigf(v.w+b.w));
}

__global__ void rowbias2_kernel(float* __restrict__ rc, const float* __restrict__ rcq,
                                const float* __restrict__ bias)
{
    int i = blockIdx.x * 256 + threadIdx.x;
    float4 b = ((const float4*)bias)[i & 255];
    float4 v = ((float4*)rc)[i];
    float4 u = ((const float4*)rcq)[i];
    ((float4*)rc)[i] = make_float4(v.x+u.x+b.x, v.y+u.y+b.y, v.z+u.z+b.z, v.w+u.w+b.w);
}

__global__ void zero_kernel(float* __restrict__ p, int n4)
{
    int i = blockIdx.x * 256 + threadIdx.x;
    if (i < n4) ((float4*)p)[i] = make_float4(0.f, 0.f, 0.f, 0.f);
}

__global__ void gruew_kernel(const float* __restrict__ gi, const float* __restrict__ gh,
                             const float* __restrict__ h,  const float* __restrict__ bih,
                             const float* __restrict__ bhh, float* __restrict__ out)
{
    int i = blockIdx.x * 256 + threadIdx.x;
    int b = i >> 10, d = i & 1023;
    float gir = gi[b*3072 + d]        + bih[d];
    float giz = gi[b*3072 + 1024 + d] + bih[1024 + d];
    float gin = gi[b*3072 + 2048 + d] + bih[2048 + d];
    float ghr = gh[b*3072 + d]        + bhh[d];
    float ghz = gh[b*3072 + 1024 + d] + bhh[1024 + d];
    float ghn = gh[b*3072 + 2048 + d] + bhh[2048 + d];
    float r = sigf(gir + ghr);
    float z = sigf(giz + ghz);
    float n = tanhfast(gin + r * ghn);
    out[i] = (1.f - z) * n + z * h[i];
}

// ---------------- host orchestration ----------------
static void tgemm(const __nv_bfloat16* Ah, const __nv_bfloat16* Al,
                  const __nv_bfloat16* Bh, const __nv_bfloat16* Bl,
                  int ldB, int kofs, float* C, int ldC, int N, int accum)
{
    dim3 g(N / 128, TB_ / 128);
    tgemm_kernel<<<g, 256, TGS_SMEM>>>(Ah, Al, Bh, Bl, ldB, kofs, C, ldC, accum);
}

static void sgemm64(const float* A, int ldA, const float* W, int ldW,
                    float* C, int ldC, int N)
{
    dim3 g(N / 64, 4);
    sgemm64_kernel<<<g, 256>>>(A, ldA, W, ldW, C, ldC);
}

extern "C" void kernel_launch(void* const* d_in, const int* in_sizes, int n_in,
                              void* d_out, int out_size)
{
    const float* c    = (const float*)d_in[0];
    const float* q    = (const float*)d_in[1];
    const float* Wb   = (const float*)d_in[2];
    const float* W1   = (const float*)d_in[3];
    const float* W1b  = (const float*)d_in[4];
    const float* W2   = (const float*)d_in[5];
    const float* W2b  = (const float*)d_in[6];
    const float* mWih = (const float*)d_in[7];
    const float* mWhh = (const float*)d_in[8];
    const float* mbih = (const float*)d_in[9];
    const float* mbhh = (const float*)d_in[10];
    const float* aWih = (const float*)d_in[11];
    const float* aWhh = (const float*)d_in[12];
    const float* abih = (const float*)d_in[13];
    const float* abhh = (const float*)d_in[14];

    cudaFuncSetAttribute(tgemm_kernel, cudaFuncAttributeMaxDynamicSharedMemorySize, TGS_SMEM);
    cudaFuncSetAttribute(scan_kernel,  cudaFuncAttributeMaxDynamicSharedMemorySize, SCAN_SMEM_BYTES);

    float *pG, *pSinv, *pS, *pGI, *pWbq, *pWbm, *prc, *prcq;
    float *ph0, *ph1, *pm, *pm2, *pgi, *pgh;
    __nv_bfloat16 *bAh, *bAl, *FAh, *FAl, *FBh, *FBl, *FCh, *FCl;
    __nv_bfloat16 *bW1h, *bW1l, *bW2h, *bW2l, *bWihh, *bWihl, *bWhhh, *bWhhl;
    __nv_bfloat16 *hAbh, *hAbl, *hBbh, *hBbl;
    cudaGetSymbolAddress((void**)&pG,    g_FAg);
    cudaGetSymbolAddress((void**)&pSinv, g_Sinv);
    cudaGetSymbolAddress((void**)&pS,    g_S);
    cudaGetSymbolAddress((void**)&pGI,   g_GI);
    cudaGetSymbolAddress((void**)&pWbq,  g_Wbq);
    cudaGetSymbolAddress((void**)&pWbm,  g_Wbm);
    cudaGetSymbolAddress((void**)&prc,   g_rc);
    cudaGetSymbolAddress((void**)&prcq,  g_rcq);
    cudaGetSymbolAddress((void**)&ph0,   g_h0);
    cudaGetSymbolAddress((void**)&ph1,   g_h1);
    cudaGetSymbolAddress((void**)&pm,    g_m);
    cudaGetSymbolAddress((void**)&pm2,   g_m2);
    cudaGetSymbolAddress((void**)&pgi,   g_gi);
    cudaGetSymbolAddress((void**)&pgh,   g_gh);
    cudaGetSymbolAddress((void**)&bAh,   g_bAh);
    cudaGetSymbolAddress((void**)&bAl,   g_bAl);
    cudaGetSymbolAddress((void**)&FAh,   g_FAh);
    cudaGetSymbolAddress((void**)&FAl,   g_FAl);
    cudaGetSymbolAddress((void**)&FBh,   g_FBh);
    cudaGetSymbolAddress((void**)&FBl,   g_FBl);
    cudaGetSymbolAddress((void**)&FCh,   g_FCh);
    cudaGetSymbolAddress((void**)&FCl,   g_FCl);
    cudaGetSymbolAddress((void**)&bW1h,  g_W1h);
    cudaGetSymbolAddress((void**)&bW1l,  g_W1l);
    cudaGetSymbolAddress((void**)&bW2h,  g_W2h);
    cudaGetSymbolAddress((void**)&bW2l,  g_W2l);
    cudaGetSymbolAddress((void**)&bWihh, g_Wihh);
    cudaGetSymbolAddress((void**)&bWihl, g_Wihl);
    cudaGetSymbolAddress((void**)&bWhhh, g_Whhh);
    cudaGetSymbolAddress((void**)&bWhhl, g_Whhl);
    cudaGetSymbolAddress((void**)&hAbh,  g_hAbh);
    cudaGetSymbolAddress((void**)&hAbl,  g_hAbl);
    cudaGetSymbolAddress((void**)&hBbh,  g_hBbh);
    cudaGetSymbolAddress((void**)&hBbl,  g_hBbl);

    const int GRID_TBD4 = (TB_ * D_ / 4) / 256;
    const int BD4  = B_ * D_ / 4;
    const int BD34 = B_ * D3_ / 4;
    const int GRID_BD4  = BD4 / 256;
    const int GRID_BD34 = BD34 / 256;
    const int GRID_BD   = (B_ * D_) / 256;
    const int BD16_BF   = (B_ * D_ * 2 / 16);   // float4 count of a bf16 [B,D] array

    cudaMemcpyAsync(pm, q, (size_t)B_ * D_ * sizeof(float), cudaMemcpyDeviceToDevice);

    // weight splits
    split_kernel<<<(D_*D9_/4)/256, 256>>>(W1, bW1h, bW1l, D_*D9_/4);
    split_kernel<<<(D_*D_/4)/256, 256>>>(W2, bW2h, bW2l, D_*D_/4);
    split_kernel<<<(D3_*D_/4)/256, 256>>>(aWih, bWihh, bWihl, D3_*D_/4);
    split_kernel<<<(D3_*D_/4)/256, 256>>>(aWhh, bWhhh, bWhhl, D3_*D_/4);

    // episode-invariant precompute
    zero_kernel<<<GRID_BD4, 256>>>(pWbq, BD4);
    sgemm64(q, D_, Wb, D_, pWbq, D_, D_);
    zero_kernel<<<GRID_BD4, 256>>>(prcq, BD4);
    sgemm64(q, D_, W1 + 2*D_, D9_, prcq, D_, D_);

    feat3b_kernel<<<GRID_TBD4, 256>>>(c, q, pWbq, FAh, FAl, FBh, FBl, FCh, FCl);
    split_kernel<<<GRID_TBD4, 256>>>(c, bAh, bAl, TB_*D_/4);

    tgemm(bAh, bAl, bW1h, bW1l, D9_, 0*D_, pSinv, D_, D_, 0);
    tgemm(bAh, bAl, bWihh, bWihl, D_, 0, pGI, D3_, D3_, 0);
    tgemm(FAh, FAl, bW1h, bW1l, D9_, 3*D_, pSinv, D_, D_, 1);
    tgemm(FBh, FBl, bW1h, bW1l, D9_, 5*D_, pSinv, D_, D_, 1);
    tgemm(FCh, FCl, bW1h, bW1l, D9_, 7*D_, pSinv, D_, D_, 1);

    float* mc = pm;
    float* mn = pm2;
    for (int ep = 0; ep < 2; ep++) {
        zero_kernel<<<GRID_BD4, 256>>>(pWbm, BD4);
        sgemm64(mc, D_, Wb, D_, pWbm, D_, D_);
        zero_kernel<<<GRID_BD4, 256>>>(prc, BD4);
        sgemm64(mc, D_, W1 + 1*D_, D9_, prc, D_, D_);
        rowbias2_kernel<<<GRID_BD4, 256>>>(prc, prcq, W1b);

        feat3b_kernel<<<GRID_TBD4, 256>>>(c, mc, pWbm, FAh, FAl, FBh, FBl, FCh, FCl);
        addrow_kernel<<<GRID_TBD4, 256>>>(pSinv, prc, pS);

        tgemm(FAh, FAl, bW1h, bW1l, D9_, 4*D_, pS, D_, D_, 1);
        tgemm(FBh, FBl, bW1h, bW1l, D9_, 6*D_, pS, D_, D_, 1);
        tgemm(FCh, FCl, bW1h, bW1l, D9_, 8*D_, pS, D_, D_, 1);

        tanhsplit_kernel<<<GRID_TBD4, 256>>>(pS, bAh, bAl);
        tgemm(bAh, bAl, bW2h, bW2l, D_, 0, pG, D_, D_, 0);
        sigbias_kernel<<<GRID_TBD4, 256>>>(pG, W2b);

        // h = 0 (fp32 + bf16 hi/lo)
        zero_kernel<<<GRID_BD4, 256>>>(ph0, BD4);
        zero_kernel<<<(BD16_BF + 255) / 256, 256>>>((float*)hAbh, BD16_BF);
        zero_kernel<<<(BD16_BF + 255) / 256, 256>>>((float*)hAbl, BD16_BF);
        reset_barrier_kernel<<<1, 1>>>();
        scan_kernel<<<128, 128, SCAN_SMEM_BYTES>>>(ph0, ph1, hAbh, hAbl, hBbh, hBbl,
                                                   pGI, pG, bWhhh, bWhhl, abih, abhh);
        // 128 steps: final h (episode output e) lands in ph0

        zero_kernel<<<GRID_BD34, 256>>>(pgi, BD34);
        sgemm64(ph0, D_, mWih, D_, pgi, D3_, D3_);
        zero_kernel<<<GRID_BD34, 256>>>(pgh, BD34);
        sgemm64(mc, D_, mWhh, D_, pgh, D3_, D3_);
        gruew_kernel<<<GRID_BD, 256>>>(pgi, pgh, mc, mbih, mbhh, mn);
        float* tmp = mc; mc = mn; mn = tmp;
    }

    cudaMemcpyAsync(d_out, mc, (size_t)B_ * D_ * sizeof(float), cudaMemcpyDeviceToDevice);
}

// round 17
// speedup vs baseline: 1.2491x; 1.0044x over previous
#include <cuda_runtime.h>
#include <cuda_bf16.h>
#include <stdint.h>

#define T_  128
#define B_  64
#define D_  1024
#define TB_ (T_*B_)
#define D3_ (3*D_)
#define D9_ (9*D_)

typedef unsigned long long ull;

// ---------------- static scratch (no allocation anywhere) ----------------
__device__ float g_FAg[TB_*D_];
__device__ float g_Sinv[TB_*D_];
__device__ float g_S[TB_*D_];
__device__ float g_GI[TB_*D3_];
__device__ float g_Wbq[B_*D_];
__device__ float g_Wbm[B_*D_];
__device__ float g_rc[B_*D_];
__device__ float g_rcq[B_*D_];
__device__ float g_h0[B_*D_];
__device__ float g_h1[B_*D_];
__device__ float g_m[B_*D_];
__device__ float g_m2[B_*D_];
__device__ float g_gi[B_*D3_];
__device__ float g_gh[B_*D3_];
__device__ int   g_barrier;

// bf16 split buffers
__device__ __nv_bfloat16 g_bAh[TB_*D_];
__device__ __nv_bfloat16 g_bAl[TB_*D_];
__device__ __nv_bfloat16 g_FAh[TB_*D_];
__device__ __nv_bfloat16 g_FAl[TB_*D_];
__device__ __nv_bfloat16 g_FBh[TB_*D_];
__device__ __nv_bfloat16 g_FBl[TB_*D_];
__device__ __nv_bfloat16 g_FCh[TB_*D_];
__device__ __nv_bfloat16 g_FCl[TB_*D_];
__device__ __nv_bfloat16 g_W1h[D_*D9_];
__device__ __nv_bfloat16 g_W1l[D_*D9_];
__device__ __nv_bfloat16 g_W2h[D_*D_];
__device__ __nv_bfloat16 g_W2l[D_*D_];
__device__ __nv_bfloat16 g_Wihh[D3_*D_];
__device__ __nv_bfloat16 g_Wihl[D3_*D_];
__device__ __nv_bfloat16 g_Whhh[D3_*D_];
__device__ __nv_bfloat16 g_Whhl[D3_*D_];
// h as bf16 hi/lo (ping-pong) for the tensor-core scan
__device__ __nv_bfloat16 g_hAbh[B_*D_];
__device__ __nv_bfloat16 g_hAbl[B_*D_];
__device__ __nv_bfloat16 g_hBbh[B_*D_];
__device__ __nv_bfloat16 g_hBbl[B_*D_];

// ---------------- helpers ----------------
__device__ __forceinline__ void ffma2(ull& c, ull a, ull b) {
    asm("fma.rn.f32x2 %0, %1, %2, %0;" : "+l"(c) : "l"(a), "l"(b));
}
__device__ __forceinline__ ull pk(float lo, float hi) {
    ull r; asm("mov.b64 %0, {%1, %2};" : "=l"(r) : "f"(lo), "f"(hi)); return r;
}
__device__ __forceinline__ float2 upk(ull a) {
    float2 v; asm("mov.b64 {%0, %1}, %2;" : "=f"(v.x), "=f"(v.y) : "l"(a)); return v;
}
__device__ __forceinline__ float sigf(float x)     { return 1.f / (1.f + __expf(-x)); }
__device__ __forceinline__ float tanhfast(float x) { return 2.f / (1.f + __expf(-2.f*x)) - 1.f; }

__device__ __forceinline__ void cpasync16(uint32_t dst, const void* src) {
    asm volatile("cp.async.cg.shared.global [%0], [%1], 16;" :: "r"(dst), "l"(src));
}
__device__ __forceinline__ void cpcommit() { asm volatile("cp.async.commit_group;"); }
__device__ __forceinline__ void cpwait1()  { asm volatile("cp.async.wait_group 1;"); }
__device__ __forceinline__ void cpwait0()  { asm volatile("cp.async.wait_group 0;"); }

__device__ __forceinline__ void ldmx4(uint32_t addr, uint32_t* r) {
    asm volatile("ldmatrix.sync.aligned.m8n8.x4.shared.b16 {%0,%1,%2,%3}, [%4];"
                 : "=r"(r[0]), "=r"(r[1]), "=r"(r[2]), "=r"(r[3]) : "r"(addr));
}
__device__ __forceinline__ void ldmx2(uint32_t addr, uint32_t* r) {
    asm volatile("ldmatrix.sync.aligned.m8n8.x2.shared.b16 {%0,%1}, [%2];"
                 : "=r"(r[0]), "=r"(r[1]) : "r"(addr));
}

#define MMA_BF16(c, a, b0, b1) \
    asm volatile("mma.sync.aligned.m16n8k16.row.col.f32.bf16.bf16.f32 " \
                 "{%0,%1,%2,%3}, {%4,%5,%6,%7}, {%8,%9}, {%0,%1,%2,%3};" \
                 : "+f"((c)[0]), "+f"((c)[1]), "+f"((c)[2]), "+f"((c)[3]) \
                 : "r"((a)[0]), "r"((a)[1]), "r"((a)[2]), "r"((a)[3]), \
                   "r"(b0), "r"(b1))

__device__ __forceinline__ void bsplit4(__nv_bfloat16* hi, __nv_bfloat16* lo, int i,
                                        float x, float y, float z, float w)
{
    __nv_bfloat16 hx = __float2bfloat16(x), hy = __float2bfloat16(y);
    __nv_bfloat16 hz = __float2bfloat16(z), hw = __float2bfloat16(w);
    ((__nv_bfloat162*)hi)[2*i]   = __nv_bfloat162(hx, hy);
    ((__nv_bfloat162*)hi)[2*i+1] = __nv_bfloat162(hz, hw);
    ((__nv_bfloat162*)lo)[2*i]   = __nv_bfloat162(__float2bfloat16(x - __bfloat162float(hx)),
                                                  __float2bfloat16(y - __bfloat162float(hy)));
    ((__nv_bfloat162*)lo)[2*i+1] = __nv_bfloat162(__float2bfloat16(z - __bfloat162float(hz)),
                                                  __float2bfloat16(w - __bfloat162float(hw)));
}

// ================= mma.sync split-bf16 GEMM (R14-exact, proven) =================
#define KC      32
#define PITCHB  80u
#define TILE_B  (128u * PITCHB)
#define BUF_B   (4u * TILE_B)
#define TGS_SMEM (2 * BUF_B)

__global__ __launch_bounds__(256) void tgemm_kernel(
    const __nv_bfloat16* __restrict__ Ah, const __nv_bfloat16* __restrict__ Al,
    const __nv_bfloat16* __restrict__ Bh, const __nv_bfloat16* __restrict__ Bl,
    int ldB, int kofs,
    float* __restrict__ C, int ldC, int accum)
{
    extern __shared__ __align__(16) char smraw[];
    const uint32_t sb = (uint32_t)__cvta_generic_to_shared(smraw);

    const int tid  = threadIdx.x;
    const int wid  = tid >> 5;
    const int lane = tid & 31;
    const int bm   = blockIdx.y * 128;
    const int bn   = blockIdx.x * 128;
    const int wm   = wid & 3;
    const int wn   = wid >> 2;

    float acc[2][8][4];
#pragma unroll
    for (int i = 0; i < 2; i++)
#pragma unroll
        for (int j = 0; j < 8; j++)
#pragma unroll
            for (int k = 0; k < 4; k++) acc[i][j][k] = 0.f;

    auto stage = [&](int buf, int k0) {
        uint32_t base = sb + (uint32_t)buf * BUF_B;
#pragma unroll
        for (int r = 0; r < 8; r++) {
            int id   = tid + 256 * r;
            int tile = id >> 9;
            int row  = (id >> 2) & 127;
            int g    = id & 3;
            uint32_t daddr = base + (uint32_t)tile * TILE_B + (uint32_t)row * PITCHB + (uint32_t)g * 16u;
            const __nv_bfloat16* src;
            if      (tile == 0) src = Ah + (size_t)(bm + row) * 1024 + k0 + g * 8;
            else if (tile == 1) src = Al + (size_t)(bm + row) * 1024 + k0 + g * 8;
            else if (tile == 2) src = Bh + (size_t)(bn + row) * ldB + kofs + k0 + g * 8;
            else                src = Bl + (size_t)(bn + row) * ldB + kofs + k0 + g * 8;
            cpasync16(daddr, src);
        }
    };

    stage(0, 0); cpcommit();

    for (int ch = 0; ch < 1024 / KC; ch++) {
        if (ch + 1 < 1024 / KC) { stage((ch + 1) & 1, (ch + 1) * KC); cpcommit(); cpwait1(); }
        else                    { cpwait0(); }
        __syncthreads();

        uint32_t base = sb + (uint32_t)(ch & 1) * BUF_B;
#pragma unroll
        for (int ks = 0; ks < 2; ks++) {
            uint32_t ah[2][4], al[2][4], bh[4][4], bl[4][4];
#pragma unroll
            for (int tm = 0; tm < 2; tm++) {
                uint32_t row = (uint32_t)(wm * 32 + tm * 16 + (lane & 15));
                uint32_t addr = base + row * PITCHB + (uint32_t)(ks * 32) + (uint32_t)((lane >> 4) * 16);
                ldmx4(addr, ah[tm]);
                ldmx4(addr + TILE_B, al[tm]);
            }
#pragma unroll
            for (int tb = 0; tb < 4; tb++) {
                uint32_t rn = (uint32_t)(wn * 64 + tb * 16 + ((lane >> 4) << 3) + (lane & 7));
                uint32_t addr = base + 2u * TILE_B + rn * PITCHB + (uint32_t)(ks * 32) + (uint32_t)(((lane >> 3) & 1) * 16);
                ldmx4(addr, bh[tb]);
                ldmx4(addr + TILE_B, bl[tb]);
            }
#pragma unroll
            for (int tm = 0; tm < 2; tm++)
#pragma unroll
                for (int tn = 0; tn < 8; tn++) {
                    int tb = tn >> 1, s = (tn & 1) * 2;
                    MMA_BF16(acc[tm][tn], ah[tm], bh[tb][s], bh[tb][s + 1]);
                    MMA_BF16(acc[tm][tn], ah[tm], bl[tb][s], bl[tb][s + 1]);
                    MMA_BF16(acc[tm][tn], al[tm], bh[tb][s], bh[tb][s + 1]);
                }
        }
        __syncthreads();
    }

    const int r0 = bm + wm * 32 + (lane >> 2);
    const int cb = bn + wn * 64 + (lane & 3) * 2;
#pragma unroll
    for (int tm = 0; tm < 2; tm++)
#pragma unroll
        for (int tn = 0; tn < 8; tn++) {
            float* p0 = C + (size_t)(r0 + tm * 16) * ldC + cb + tn * 8;
            float* p1 = p0 + 8 * (size_t)ldC;
            if (accum) {
                float2 d0 = *(float2*)p0;
                d0.x += acc[tm][tn][0]; d0.y += acc[tm][tn][1];
                *(float2*)p0 = d0;
                float2 d1 = *(float2*)p1;
                d1.x += acc[tm][tn][2]; d1.y += acc[tm][tn][3];
                *(float2*)p1 = d1;
            } else {
                *(float2*)p0 = make_float2(acc[tm][tn][0], acc[tm][tn][1]);
                *(float2*)p1 = make_float2(acc[tm][tn][2], acc[tm][tn][3]);
            }
        }
}

// ================= persistent scan kernel v5: warp-specialized tensor-core =================
// 128 blocks x 256 threads. Warps 0-3 = consumers (MMA + epilogue, R16-identical math),
// warps 4-7 = producers (h cp.async staging only). One sync per chunk.
#define SCW_PER 1920u
#define SCW_BYTES (8u*4u*2u*SCW_PER)       // 122,880
#define SCH_PER 5120u
#define SCH_BUF (4u*2u*SCH_PER)            // 40,960 per buffer
#define SCAN_SMEM_BYTES (SCW_BYTES + 2u*SCH_BUF)   // 204,800

__device__ __forceinline__ uint32_t WT(int chunk, int sub, int op, int row) {
    return (uint32_t)(((chunk*4 + sub)*2 + op)) * SCW_PER + (uint32_t)row * 80u;
}
__device__ __forceinline__ uint32_t HT(int buf, int sub, int op, int row) {
    return SCW_BYTES + (uint32_t)buf * SCH_BUF + (uint32_t)((sub*2 + op)) * SCH_PER + (uint32_t)row * 80u;
}

__global__ __launch_bounds__(256) void scan_kernel(
    float* hA, float* hB,
    __nv_bfloat16* hAbh, __nv_bfloat16* hAbl,
    __nv_bfloat16* hBbh, __nv_bfloat16* hBbl,
    const float* __restrict__ GI, const float* __restrict__ GG,
    const __nv_bfloat16* __restrict__ Whhh, const __nv_bfloat16* __restrict__ Whhl,
    const float* __restrict__ bih, const float* __restrict__ bhh)
{
    extern __shared__ __align__(16) char smraw[];
    const uint32_t sb = (uint32_t)__cvta_generic_to_shared(smraw);

    const int tid  = threadIdx.x;
    const int wid  = tid >> 5;
    const int lane = tid & 31;
    const bool producer = (wid >= 4);
    const int w    = wid & 3;
    const int ptid = tid - 128;            // producer-local id (valid when producer)
    const int bd0  = blockIdx.x * 8;

    // ---- load Whh slice (hi+lo) once: 6144 16B-granules, all 256 threads ----
    for (int i = tid; i < 6144; i += 256) {
        int op  = i / 3072;
        int rem = i - op * 3072;
        int row = rem >> 7;
        int g   = rem & 127;
        int k   = g * 8;
        int chunk = k >> 7, kin = k & 127, sub = kin >> 5, kins = kin & 31;
        uint32_t dst = sb + WT(chunk, sub, op, row) + (uint32_t)((kins >> 3) * 16);
        int gate = row >> 3, dd = row & 7;
        const __nv_bfloat16* src = (op ? Whhl : Whhh) + (size_t)(gate * 1024 + bd0 + dd) * 1024 + k;
        cpasync16(dst, src);
    }
    cpcommit(); cpwait0();
    __syncthreads();

    // consumer (b, d) coverage
    const int b0 = w * 16 + (lane >> 2);
    const int b1 = b0 + 8;
    const int d0 = bd0 + 2 * (lane & 3);
    const int d1 = d0 + 1;
    const float bir[2] = { bih[d0],        bih[d1] };
    const float biz[2] = { bih[1024 + d0], bih[1024 + d1] };
    const float bin[2] = { bih[2048 + d0], bih[2048 + d1] };
    const float bhr[2] = { bhh[d0],        bhh[d1] };
    const float bhz[2] = { bhh[1024 + d0], bhh[1024 + d1] };
    const float bhn[2] = { bhh[2048 + d0], bhh[2048 + d1] };

    for (int t = 0; t < T_; t++) {
        const float* hf_in = (t & 1) ? hB : hA;
        float*       hf_out = (t & 1) ? hA : hB;
        const __nv_bfloat16* hh_in = (t & 1) ? hBbh : hAbh;
        const __nv_bfloat16* hl_in = (t & 1) ? hBbl : hAbl;
        __nv_bfloat16* hh_out = (t & 1) ? hAbh : hBbh;
        __nv_bfloat16* hl_out = (t & 1) ? hAbl : hBbl;
        const float* gi_t = GI + (size_t)t * B_ * D3_;
        const float* gg_t = GG + (size_t)t * B_ * D_;

        // producer staging: 2048 granules over 128 producer threads
        auto stageh = [&](int buf, int k0) {
#pragma unroll
            for (int r = 0; r < 16; r++) {
                int id  = ptid + 128 * r;
                int op  = id >> 10;
                int row = (id >> 4) & 63;
                int g   = id & 15;
                int sub = g >> 2;
                uint32_t dst = sb + HT(buf, sub, op, row) + (uint32_t)((g & 3) * 16);
                const __nv_bfloat16* src = (op ? hl_in : hh_in) + (size_t)row * 1024 + k0 + g * 8;
                cpasync16(dst, src);
            }
        };

        float hp[2][2], gir[2][2], giz[2][2], gin[2][2], G[2][2];
        float acc[3][4];

        if (producer) {
            stageh(0, 0); cpcommit(); cpwait0();
        } else {
            // prefetch epilogue operands while producers stage chunk 0
#pragma unroll
            for (int i = 0; i < 2; i++) {
                int b = i ? b1 : b0;
#pragma unroll
                for (int e = 0; e < 2; e++) {
                    int d = e ? d1 : d0;
                    hp[i][e]  = hf_in[b * 1024 + d];
                    gir[i][e] = gi_t[b * 3072 + d];
                    giz[i][e] = gi_t[b * 3072 + 1024 + d];
                    gin[i][e] = gi_t[b * 3072 + 2048 + d];
                    G[i][e]   = gg_t[b * 1024 + d];
                }
            }
#pragma unroll
            for (int n = 0; n < 3; n++)
#pragma unroll
                for (int k = 0; k < 4; k++) acc[n][k] = 0.f;
        }
        __syncthreads();   // buf0 ready

        for (int ch = 0; ch < 8; ch++) {
            if (producer) {
                if (ch + 1 < 8) { stageh((ch + 1) & 1, (ch + 1) * 128); cpcommit(); cpwait0(); }
            } else {
                const int buf = ch & 1;
#pragma unroll
                for (int ks = 0; ks < 8; ks++) {
                    const int sub = ks >> 1;
                    const uint32_t kso = (uint32_t)((ks & 1) * 32);
                    uint32_t ah[4], al[4], bh01[4], bl01[4], bh2[2], bl2[2];
                    {
                        uint32_t arow = (uint32_t)(w * 16 + (lane & 15));
                        uint32_t a0 = sb + HT(buf, sub, 0, 0) + arow * 80u + kso + (uint32_t)((lane >> 4) * 16);
                        ldmx4(a0, ah);
                        ldmx4(a0 + SCH_PER, al);
                    }
                    {
                        uint32_t brow = (uint32_t)(((lane >> 4) << 3) + (lane & 7));
                        uint32_t koff = kso + (uint32_t)(((lane >> 3) & 1) * 16);
                        uint32_t bA = sb + WT(ch, sub, 0, 0) + brow * 80u + koff;
                        ldmx4(bA, bh01);
                        ldmx4(bA + SCW_PER, bl01);
                        uint32_t brow2 = (uint32_t)(16 + (lane & 7));
                        uint32_t bB = sb + WT(ch, sub, 0, 0) + brow2 * 80u + koff;
                        ldmx2(bB, bh2);
                        ldmx2(bB + SCW_PER, bl2);
                    }
                    MMA_BF16(acc[0], ah, bh01[0], bh01[1]);
                    MMA_BF16(acc[0], ah, bl01[0], bl01[1]);
                    MMA_BF16(acc[0], al, bh01[0], bh01[1]);
                    MMA_BF16(acc[1], ah, bh01[2], bh01[3]);
                    MMA_BF16(acc[1], ah, bl01[2], bl01[3]);
                    MMA_BF16(acc[1], al, bh01[2], bh01[3]);
                    MMA_BF16(acc[2], ah, bh2[0], bh2[1]);
                    MMA_BF16(acc[2], ah, bl2[0], bl2[1]);
                    MMA_BF16(acc[2], al, bh2[0], bh2[1]);
                }
            }
            __syncthreads();   // buf[(ch+1)&1] ready; buf[ch&1] consumed
        }

        if (!producer) {
            // epilogue: acc[gate][i*2+e] = dot for (b_i, d_e)
#pragma unroll
            for (int i = 0; i < 2; i++) {
                int b = i ? b1 : b0;
#pragma unroll
                for (int e = 0; e < 2; e++) {
                    int d = e ? d1 : d0;
                    float dr = acc[0][i * 2 + e];
                    float dz = acc[1][i * 2 + e];
                    float dn = acc[2][i * 2 + e];
                    float r = sigf(gir[i][e] + bir[e] + dr + bhr[e]);
                    float z = sigf(giz[i][e] + biz[e] + dz + bhz[e]);
                    float n = tanhfast(gin[i][e] + bin[e] + r * (dn + bhn[e]));
                    float hatt = (1.f - z) * n + z * hp[i][e];
                    float hnew = G[i][e] * hatt + (1.f - G[i][e]) * hp[i][e];
                    hf_out[b * 1024 + d] = hnew;
                    __nv_bfloat16 hh = __float2bfloat16(hnew);
                    hh_out[b * 1024 + d] = hh;
                    hl_out[b * 1024 + d] = __float2bfloat16(hnew - __bfloat162float(hh));
                }
            }
        }

        // grid barrier (monotonic counter; 128 CTAs all resident at 1 CTA/SM)
        __syncthreads();
        __threadfence();
        if (tid == 0) {
            atomicAdd(&g_barrier, 1);
            volatile int* bp = &g_barrier;
            int target = 128 * (t + 1);
            while (*bp < target) __nanosleep(32);
        }
        __syncthreads();
        __threadfence();
    }
}

__global__ void reset_barrier_kernel() { g_barrier = 0; }

// ---------------- small M=64 split-K GEMM (R14-exact) ----------------
__global__ __launch_bounds__(256) void sgemm64_kernel(
    const float* __restrict__ A, int ldA,
    const float* __restrict__ W, int ldW,
    float* __restrict__ C, int ldC)
{
    __shared__ float As[16][68];
    __shared__ float Ws[16][68];
    const int tid = threadIdx.x;
    const int bn = blockIdx.x * 64;
    const int k0 = blockIdx.y * 256;
    const int tx = tid & 15, ty = tid >> 4;
    const int m0 = ty * 4, n0 = tx * 4;
    const int lrow = tid >> 2, lk = (tid & 3) * 4;

    ull acc[2][4];
#pragma unroll
    for (int i = 0; i < 2; i++)
#pragma unroll
        for (int j = 0; j < 4; j++) acc[i][j] = 0ull;

    for (int kc = 0; kc < 256; kc += 16) {
        float4 av = *(const float4*)(A + (size_t)lrow * ldA + k0 + kc + lk);
        float4 wv = *(const float4*)(W + (size_t)(bn + lrow) * ldW + k0 + kc + lk);
        __syncthreads();
        As[lk+0][lrow] = av.x; As[lk+1][lrow] = av.y; As[lk+2][lrow] = av.z; As[lk+3][lrow] = av.w;
        Ws[lk+0][lrow] = wv.x; Ws[lk+1][lrow] = wv.y; Ws[lk+2][lrow] = wv.z; Ws[lk+3][lrow] = wv.w;
        __syncthreads();
#pragma unroll
        for (int kk = 0; kk < 16; kk++) {
            ull a01 = *(const ull*)&As[kk][m0];
            ull a23 = *(const ull*)&As[kk][m0 + 2];
            float4 w4 = *(const float4*)&Ws[kk][n0];
            ull w0 = pk(w4.x, w4.x), w1 = pk(w4.y, w4.y);
            ull w2 = pk(w4.z, w4.z), w3 = pk(w4.w, w4.w);
            ffma2(acc[0][0], a01, w0); ffma2(acc[0][1], a01, w1);
            ffma2(acc[0][2], a01, w2); ffma2(acc[0][3], a01, w3);
            ffma2(acc[1][0], a23, w0); ffma2(acc[1][1], a23, w1);
            ffma2(acc[1][2], a23, w2); ffma2(acc[1][3], a23, w3);
        }
    }
#pragma unroll
    for (int j = 0; j < 4; j++) {
        float2 v0 = upk(acc[0][j]);
        float2 v1 = upk(acc[1][j]);
        atomicAdd(&C[(size_t)(m0 + 0) * ldC + bn + n0 + j], v0.x);
        atomicAdd(&C[(size_t)(m0 + 1) * ldC + bn + n0 + j], v0.y);
        atomicAdd(&C[(size_t)(m0 + 2) * ldC + bn + n0 + j], v1.x);
        atomicAdd(&C[(size_t)(m0 + 3) * ldC + bn + n0 + j], v1.y);
    }
}

// ---------------- elementwise kernels ----------------
__global__ void split_kernel(const float* __restrict__ s, __nv_bfloat16* __restrict__ hi,
                             __nv_bfloat16* __restrict__ lo, int n4)
{
    int i = blockIdx.x * 256 + threadIdx.x;
    if (i >= n4) return;
    float4 v = ((const float4*)s)[i];
    bsplit4(hi, lo, i, v.x, v.y, v.z, v.w);
}

__global__ void feat3b_kernel(const float* __restrict__ c, const float* __restrict__ x,
                              const float* __restrict__ y,
                              __nv_bfloat16* __restrict__ FAh, __nv_bfloat16* __restrict__ FAl,
                              __nv_bfloat16* __restrict__ FBh, __nv_bfloat16* __restrict__ FBl,
                              __nv_bfloat16* __restrict__ FCh, __nv_bfloat16* __restrict__ FCl)
{
    int i = blockIdx.x * 256 + threadIdx.x;
    int bc = ((i >> 8) & 63) * 256 + (i & 255);
    float4 cv = ((const float4*)c)[i];
    float4 xv = ((const float4*)x)[bc];
    float4 yv = ((const float4*)y)[bc];
    bsplit4(FAh, FAl, i, cv.x*xv.x, cv.y*xv.y, cv.z*xv.z, cv.w*xv.w);
    bsplit4(FBh, FBl, i, fabsf(cv.x-xv.x), fabsf(cv.y-xv.y), fabsf(cv.z-xv.z), fabsf(cv.w-xv.w));
    bsplit4(FCh, FCl, i, cv.x*yv.x, cv.y*yv.y, cv.z*yv.z, cv.w*yv.w);
}

__global__ void addrow_kernel(const float* __restrict__ S0, const float* __restrict__ rc,
                              float* __restrict__ S)
{
    int i = blockIdx.x * 256 + threadIdx.x;
    int bc = ((i >> 8) & 63) * 256 + (i & 255);
    float4 a = ((const float4*)S0)[i];
    float4 r = ((const float4*)rc)[bc];
    ((float4*)S)[i] = make_float4(a.x+r.x, a.y+r.y, a.z+r.z, a.w+r.w);
}

__global__ void tanhsplit_kernel(const float* __restrict__ S,
                                 __nv_bfloat16* __restrict__ hi, __nv_bfloat16* __restrict__ lo)
{
    int i = blockIdx.x * 256 + threadIdx.x;
    float4 v = ((const float4*)S)[i];
    bsplit4(hi, lo, i, tanhfast(v.x), tanhfast(v.y), tanhfast(v.z), tanhfast(v.w));
}

__global__ void sigbias_kernel(float* __restrict__ G, const float* __restrict__ bias)
{
    int i = blockIdx.x * 256 + threadIdx.x;
    float4 b = ((const float4*)bias)[i & 255];
    float4 v = ((float4*)G)[i];
    ((float4*)G)[i] = make_float4(sigf(v.x+b.x), sigf(v.y+b.y), sigf(v.z+b.z), sigf(v.w+b.w));
}

__global__ void rowbias2_kernel(float* __restrict__ rc, const float* __restrict__ rcq,
                                const float* __restrict__ bias)
{
    int i = blockIdx.x * 256 + threadIdx.x;
    float4 b = ((const float4*)bias)[i & 255];
    float4 v = ((float4*)rc)[i];
    float4 u = ((const float4*)rcq)[i];
    ((float4*)rc)[i] = make_float4(v.x+u.x+b.x, v.y+u.y+b.y, v.z+u.z+b.z, v.w+u.w+b.w);
}

__global__ void zero_kernel(float* __restrict__ p, int n4)
{
    int i = blockIdx.x * 256 + threadIdx.x;
    if (i < n4) ((float4*)p)[i] = make_float4(0.f, 0.f, 0.f, 0.f);
}

__global__ void gruew_kernel(const float* __restrict__ gi, const float* __restrict__ gh,
                             const float* __restrict__ h,  const float* __restrict__ bih,
                             const float* __restrict__ bhh, float* __restrict__ out)
{
    int i = blockIdx.x * 256 + threadIdx.x;
    int b = i >> 10, d = i & 1023;
    float gir = gi[b*3072 + d]        + bih[d];
    float giz = gi[b*3072 + 1024 + d] + bih[1024 + d];
    float gin = gi[b*3072 + 2048 + d] + bih[2048 + d];
    float ghr = gh[b*3072 + d]        + bhh[d];
    float ghz = gh[b*3072 + 1024 + d] + bhh[1024 + d];
    float ghn = gh[b*3072 + 2048 + d] + bhh[2048 + d];
    float r = sigf(gir + ghr);
    float z = sigf(giz + ghz);
    float n = tanhfast(gin + r * ghn);
    out[i] = (1.f - z) * n + z * h[i];
}

// ---------------- host orchestration ----------------
static void tgemm(const __nv_bfloat16* Ah, const __nv_bfloat16* Al,
                  const __nv_bfloat16* Bh, const __nv_bfloat16* Bl,
                  int ldB, int kofs, float* C, int ldC, int N, int accum)
{
    dim3 g(N / 128, TB_ / 128);
    tgemm_kernel<<<g, 256, TGS_SMEM>>>(Ah, Al, Bh, Bl, ldB, kofs, C, ldC, accum);
}

static void sgemm64(const float* A, int ldA, const float* W, int ldW,
                    float* C, int ldC, int N)
{
    dim3 g(N / 64, 4);
    sgemm64_kernel<<<g, 256>>>(A, ldA, W, ldW, C, ldC);
}

extern "C" void kernel_launch(void* const* d_in, const int* in_sizes, int n_in,
                              void* d_out, int out_size)
{
    const float* c    = (const float*)d_in[0];
    const float* q    = (const float*)d_in[1];
    const float* Wb   = (const float*)d_in[2];
    const float* W1   = (const float*)d_in[3];
    const float* W1b  = (const float*)d_in[4];
    const float* W2   = (const float*)d_in[5];
    const float* W2b  = (const float*)d_in[6];
    const float* mWih = (const float*)d_in[7];
    const float* mWhh = (const float*)d_in[8];
    const float* mbih = (const float*)d_in[9];
    const float* mbhh = (const float*)d_in[10];
    const float* aWih = (const float*)d_in[11];
    const float* aWhh = (const float*)d_in[12];
    const float* abih = (const float*)d_in[13];
    const float* abhh = (const float*)d_in[14];

    cudaFuncSetAttribute(tgemm_kernel, cudaFuncAttributeMaxDynamicSharedMemorySize, TGS_SMEM);
    cudaFuncSetAttribute(scan_kernel,  cudaFuncAttributeMaxDynamicSharedMemorySize, SCAN_SMEM_BYTES);

    float *pG, *pSinv, *pS, *pGI, *pWbq, *pWbm, *prc, *prcq;
    float *ph0, *ph1, *pm, *pm2, *pgi, *pgh;
    __nv_bfloat16 *bAh, *bAl, *FAh, *FAl, *FBh, *FBl, *FCh, *FCl;
    __nv_bfloat16 *bW1h, *bW1l, *bW2h, *bW2l, *bWihh, *bWihl, *bWhhh, *bWhhl;
    __nv_bfloat16 *hAbh, *hAbl, *hBbh, *hBbl;
    cudaGetSymbolAddress((void**)&pG,    g_FAg);
    cudaGetSymbolAddress((void**)&pSinv, g_Sinv);
    cudaGetSymbolAddress((void**)&pS,    g_S);
    cudaGetSymbolAddress((void**)&pGI,   g_GI);
    cudaGetSymbolAddress((void**)&pWbq,  g_Wbq);
    cudaGetSymbolAddress((void**)&pWbm,  g_Wbm);
    cudaGetSymbolAddress((void**)&prc,   g_rc);
    cudaGetSymbolAddress((void**)&prcq,  g_rcq);
    cudaGetSymbolAddress((void**)&ph0,   g_h0);
    cudaGetSymbolAddress((void**)&ph1,   g_h1);
    cudaGetSymbolAddress((void**)&pm,    g_m);
    cudaGetSymbolAddress((void**)&pm2,   g_m2);
    cudaGetSymbolAddress((void**)&pgi,   g_gi);
    cudaGetSymbolAddress((void**)&pgh,   g_gh);
    cudaGetSymbolAddress((void**)&bAh,   g_bAh);
    cudaGetSymbolAddress((void**)&bAl,   g_bAl);
    cudaGetSymbolAddress((void**)&FAh,   g_FAh);
    cudaGetSymbolAddress((void**)&FAl,   g_FAl);
    cudaGetSymbolAddress((void**)&FBh,   g_FBh);
    cudaGetSymbolAddress((void**)&FBl,   g_FBl);
    cudaGetSymbolAddress((void**)&FCh,   g_FCh);
    cudaGetSymbolAddress((void**)&FCl,   g_FCl);
    cudaGetSymbolAddress((void**)&bW1h,  g_W1h);
    cudaGetSymbolAddress((void**)&bW1l,  g_W1l);
    cudaGetSymbolAddress((void**)&bW2h,  g_W2h);
    cudaGetSymbolAddress((void**)&bW2l,  g_W2l);
    cudaGetSymbolAddress((void**)&bWihh, g_Wihh);
    cudaGetSymbolAddress((void**)&bWihl, g_Wihl);
    cudaGetSymbolAddress((void**)&bWhhh, g_Whhh);
    cudaGetSymbolAddress((void**)&bWhhl, g_Whhl);
    cudaGetSymbolAddress((void**)&hAbh,  g_hAbh);
    cudaGetSymbolAddress((void**)&hAbl,  g_hAbl);
    cudaGetSymbolAddress((void**)&hBbh,  g_hBbh);
    cudaGetSymbolAddress((void**)&hBbl,  g_hBbl);

    const int GRID_TBD4 = (TB_ * D_ / 4) / 256;
    const int BD4  = B_ * D_ / 4;
    const int BD34 = B_ * D3_ / 4;
    const int GRID_BD4  = BD4 / 256;
    const int GRID_BD34 = BD34 / 256;
    const int GRID_BD   = (B_ * D_) / 256;
    const int BD16_BF   = (B_ * D_ * 2 / 16);

    cudaMemcpyAsync(pm, q, (size_t)B_ * D_ * sizeof(float), cudaMemcpyDeviceToDevice);

    // weight splits
    split_kernel<<<(D_*D9_/4)/256, 256>>>(W1, bW1h, bW1l, D_*D9_/4);
    split_kernel<<<(D_*D_/4)/256, 256>>>(W2, bW2h, bW2l, D_*D_/4);
    split_kernel<<<(D3_*D_/4)/256, 256>>>(aWih, bWihh, bWihl, D3_*D_/4);
    split_kernel<<<(D3_*D_/4)/256, 256>>>(aWhh, bWhhh, bWhhl, D3_*D_/4);

    // episode-invariant precompute
    zero_kernel<<<GRID_BD4, 256>>>(pWbq, BD4);
    sgemm64(q, D_, Wb, D_, pWbq, D_, D_);
    zero_kernel<<<GRID_BD4, 256>>>(prcq, BD4);
    sgemm64(q, D_, W1 + 2*D_, D9_, prcq, D_, D_);

    feat3b_kernel<<<GRID_TBD4, 256>>>(c, q, pWbq, FAh, FAl, FBh, FBl, FCh, FCl);
    split_kernel<<<GRID_TBD4, 256>>>(c, bAh, bAl, TB_*D_/4);

    tgemm(bAh, bAl, bW1h, bW1l, D9_, 0*D_, pSinv, D_, D_, 0);
    tgemm(bAh, bAl, bWihh, bWihl, D_, 0, pGI, D3_, D3_, 0);
    tgemm(FAh, FAl, bW1h, bW1l, D9_, 3*D_, pSinv, D_, D_, 1);
    tgemm(FBh, FBl, bW1h, bW1l, D9_, 5*D_, pSinv, D_, D_, 1);
    tgemm(FCh, FCl, bW1h, bW1l, D9_, 7*D_, pSinv, D_, D_, 1);

    float* mc = pm;
    float* mn = pm2;
    for (int ep = 0; ep < 2; ep++) {
        zero_kernel<<<GRID_BD4, 256>>>(pWbm, BD4);
        sgemm64(mc, D_, Wb, D_, pWbm, D_, D_);
        zero_kernel<<<GRID_BD4, 256>>>(prc, BD4);
        sgemm64(mc, D_, W1 + 1*D_, D9_, prc, D_, D_);
        rowbias2_kernel<<<GRID_BD4, 256>>>(prc, prcq, W1b);

        feat3b_kernel<<<GRID_TBD4, 256>>>(c, mc, pWbm, FAh, FAl, FBh, FBl, FCh, FCl);
        addrow_kernel<<<GRID_TBD4, 256>>>(pSinv, prc, pS);

        tgemm(FAh, FAl, bW1h, bW1l, D9_, 4*D_, pS, D_, D_, 1);
        tgemm(FBh, FBl, bW1h, bW1l, D9_, 6*D_, pS, D_, D_, 1);
        tgemm(FCh, FCl, bW1h, bW1l, D9_, 8*D_, pS, D_, D_, 1);

        tanhsplit_kernel<<<GRID_TBD4, 256>>>(pS, bAh, bAl);
        tgemm(bAh, bAl, bW2h, bW2l, D_, 0, pG, D_, D_, 0);
        sigbias_kernel<<<GRID_TBD4, 256>>>(pG, W2b);

        // h = 0 (fp32 + bf16 hi/lo)
        zero_kernel<<<GRID_BD4, 256>>>(ph0, BD4);
        zero_kernel<<<(BD16_BF + 255) / 256, 256>>>((float*)hAbh, BD16_BF);
        zero_kernel<<<(BD16_BF + 255) / 256, 256>>>((float*)hAbl, BD16_BF);
        reset_barrier_kernel<<<1, 1>>>();
        scan_kernel<<<128, 256, SCAN_SMEM_BYTES>>>(ph0, ph1, hAbh, hAbl, hBbh, hBbl,
                                                   pGI, pG, bWhhh, bWhhl, abih, abhh);
        // 128 steps: final h (episode output e) lands in ph0

        zero_kernel<<<GRID_BD34, 256>>>(pgi, BD34);
        sgemm64(ph0, D_, mWih, D_, pgi, D3_, D3_);
        zero_kernel<<<GRID_BD34, 256>>>(pgh, BD34);
        sgemm64(mc, D_, mWhh, D_, pgh, D3_, D3_);
        gruew_kernel<<<GRID_BD, 256>>>(pgi, pgh, mc, mbih, mbhh, mn);
        float* tmp = mc; mc = mn; mn = tmp;
    }

    cudaMemcpyAsync(d_out, mc, (size_t)B_ * D_ * sizeof(float), cudaMemcpyDeviceToDevice);
}